// round 11
// baseline (speedup 1.0000x reference)
#include <cuda_runtime.h>
#include <cuda_fp16.h>
#include <cstdint>

// TT layer via merged-core fp16 mma.sync GEMMs (m16n8k16, fp32 accumulate).
// Round 11: 64x64 warp tiles (8 warps, CTA 128x256, 1 CTA/SM) -> LDSM
// wavefronts per MMA drop 1.5x. GEMM1 keeps resident A + 8-sample streaming.
// out[n,ab,cd] = relu( sum H12[ab,(s,ij)] x[n,ij,kl] H34[(cd,s),kl] + bias )
// GEMM1 per n: M1[cds, ij] = H34 . Xr[n]^T   M=1024 N=256 K=256
// GEMM2 per n: out[ab, cd] = H12 . M1[n]^T   M=256  N=256 K=1024 (+bias,relu)

__device__ __half g_H34[262144];
__device__ __half g_H12[262144];
__device__ __half g_Xr[67108864];   // RNE-rounded x (128 MB)
__device__ __half g_M1[268435456];  // M1 fp16 (512 MB)

__device__ __forceinline__ uint32_t smem_u32(const void* p) {
  uint32_t a;
  asm("{ .reg .u64 t; cvta.to.shared.u64 t, %1; cvt.u32.u64 %0, t; }" : "=r"(a) : "l"(p));
  return a;
}
__device__ __forceinline__ void cp16(uint32_t s, const __half* g) {
  asm volatile("cp.async.cg.shared.global [%0], [%1], 16;" :: "r"(s), "l"(g));
}
__device__ __forceinline__ void mma_f16(float* c, const uint32_t* a, uint32_t b0, uint32_t b1) {
  asm volatile(
      "mma.sync.aligned.m16n8k16.row.col.f32.f16.f16.f32 "
      "{%0,%1,%2,%3}, {%4,%5,%6,%7}, {%8,%9}, {%0,%1,%2,%3};"
      : "+f"(c[0]), "+f"(c[1]), "+f"(c[2]), "+f"(c[3])
      : "r"(a[0]), "r"(a[1]), "r"(a[2]), "r"(a[3]), "r"(b0), "r"(b1));
}
__device__ __forceinline__ void ldsm_x4(uint32_t* r, uint32_t addr) {
  asm volatile("ldmatrix.sync.aligned.m8n8.x4.shared.b16 {%0,%1,%2,%3}, [%4];"
               : "=r"(r[0]), "=r"(r[1]), "=r"(r[2]), "=r"(r[3]) : "r"(addr));
}

// ---------------- precompute (fp32 math, RNE fp16 store) ----------------
__global__ void prep_h34(const float* __restrict__ G3, const float* __restrict__ G4) {
  int e = blockIdx.x * 256 + threadIdx.x;
  int col = e & 255, row = e >> 8;
  int s = row & 3, cd = row >> 2;
  int c = cd >> 4, d = cd & 15, k = col >> 4, l = col & 15;
  float acc = 0.f;
#pragma unroll
  for (int tt = 0; tt < 4; ++tt)
    acc += G3[((c * 16 + k) * 4 + s) * 4 + tt] * G4[(d * 16 + l) * 4 + tt];
  g_H34[e] = __float2half_rn(acc);
}
__global__ void prep_h12(const float* __restrict__ G1, const float* __restrict__ G2) {
  int e = blockIdx.x * 256 + threadIdx.x;
  int ab = e >> 10, k = e & 1023;
  int s = k >> 8, ij = k & 255;
  int a = ab >> 4, b = ab & 15, i = ij >> 4, j = ij & 15;
  float acc = 0.f;
#pragma unroll
  for (int r = 0; r < 4; ++r)
    acc += G1[(a * 16 + i) * 4 + r] * G2[((b * 16 + j) * 4 + r) * 4 + s];
  g_H12[e] = __float2half_rn(acc);
}
__global__ __launch_bounds__(256) void round_x(const float* __restrict__ x) {
  size_t idx = (size_t)blockIdx.x * 256 + threadIdx.x;
  float4 v = *(const float4*)(x + idx * 4);
  __half2 h0 = __floats2half2_rn(v.x, v.y);
  __half2 h1 = __floats2half2_rn(v.z, v.w);
  uint2 o = { *(uint32_t*)&h0, *(uint32_t*)&h1 };
  *(uint2*)(g_Xr + idx * 4) = o;
}

#define PADH 40
#define PADA 264          // resident A row stride (256 + 8 halves)
#define A_RES_H 33792     // 128 * PADA
#define B1_STG_H 10240    // GEMM1 B stage: 256 rows * PADH
#define NGRP 8            // samples per GEMM1 CTA

// ================= GEMM1: M1[n] = H34_mtile . Xr[n]^T =================
// CTA: 8 warps (2m x 4n), tile 128(m) x 256(n, full). A resident.
// K=256 = 8 chunks; NGRP samples streamed, continuous 4-stage B pipeline.
__global__ __launch_bounds__(256, 1) void tt_gemm1(
    const __half* __restrict__ A, const __half* __restrict__ B,
    __half* __restrict__ C) {
  extern __shared__ __align__(16) __half smh[];
  const int t = threadIdx.x;
  const int lane = t & 31, wid = t >> 5;
  const int grp = lane >> 2, tg = lane & 3;
  const int mt = blockIdx.x;
  const int nbase = blockIdx.y * NGRP;
  const int wm = (wid & 1) * 64, wn = (wid >> 1) * 64;

  const uint32_t base = smem_u32(smh);
  const uint32_t bbase = base + A_RES_H * 2u;

  // resident A tile: 128 rows x 256 halves
  {
    const __half* Am = A + (long long)mt * 128 * 256;
#pragma unroll
    for (int rep = 0; rep < 16; ++rep) {
      int idx = rep * 256 + t;
      int row = idx >> 5, seg = idx & 31;
      cp16(base + (uint32_t)(row * PADA + seg * 8) * 2u, Am + row * 256 + seg * 8);
    }
    asm volatile("cp.async.commit_group;" ::: "memory");
  }

  uint32_t aOff[4];
#pragma unroll
  for (int mi = 0; mi < 4; ++mi)
    aOff[mi] = (uint32_t)((wm + mi * 16 + (lane & 15)) * PADA + (lane >> 4) * 8) * 2u;
  uint32_t bOff[4];
#pragma unroll
  for (int q = 0; q < 4; ++q)
    bOff[q] = (uint32_t)((wn + q * 16 + (lane & 7) + ((lane >> 4) << 3)) * PADH +
                         (((lane >> 3) & 1) << 3)) * 2u;

  // B loader: 256 rows x 32 halves per chunk; srow = t>>2 (+64/rep), sq = t&3
  const int srow = t >> 2, sq = t & 3;
  const uint32_t stB = bbase + (uint32_t)(srow * PADH + sq * 8) * 2u;

#pragma unroll
  for (int pch = 0; pch < 3; ++pch) {  // chunks 0..2 of sample nbase
    const __half* gb = B + (long long)nbase * 65536 + pch * 32;
    const uint32_t so = (uint32_t)pch * B1_STG_H * 2u;
#pragma unroll
    for (int rep = 0; rep < 4; ++rep)
      cp16(stB + so + rep * 64u * PADH * 2u, gb + (long long)(srow + rep * 64) * 256 + sq * 8);
    asm volatile("cp.async.commit_group;" ::: "memory");
  }

  float acc[4][8][4];
#pragma unroll
  for (int mi = 0; mi < 4; ++mi)
#pragma unroll
    for (int ni = 0; ni < 8; ++ni)
#pragma unroll
      for (int q = 0; q < 4; ++q) acc[mi][ni][q] = 0.f;

  for (int gc = 0; gc < 8 * NGRP; ++gc) {
    const int ch = gc & 7;
    asm volatile("cp.async.wait_group 2;" ::: "memory");
    __syncthreads();

    if (gc + 3 < 8 * NGRP) {
      int g2 = gc + 3;
      const __half* gb = B + (long long)(nbase + (g2 >> 3)) * 65536 + (g2 & 7) * 32;
      const uint32_t so = (uint32_t)(g2 & 3) * B1_STG_H * 2u;
#pragma unroll
      for (int rep = 0; rep < 4; ++rep)
        cp16(stB + so + rep * 64u * PADH * 2u, gb + (long long)(srow + rep * 64) * 256 + sq * 8);
    }
    asm volatile("cp.async.commit_group;" ::: "memory");

    const uint32_t sa = base + (uint32_t)ch * 64u;   // +32 halves per chunk
    const uint32_t sb = bbase + (uint32_t)(gc & 3) * B1_STG_H * 2u;
#pragma unroll
    for (int sel = 0; sel < 2; ++sel) {
      const uint32_t ko = (uint32_t)sel * 32u;
      uint32_t a[4][4], b[4][4];
#pragma unroll
      for (int mi = 0; mi < 4; ++mi) ldsm_x4(a[mi], sa + aOff[mi] + ko);
#pragma unroll
      for (int q = 0; q < 4; ++q) ldsm_x4(b[q], sb + bOff[q] + ko);
#pragma unroll
      for (int q = 0; q < 4; ++q)
#pragma unroll
        for (int mi = 0; mi < 4; ++mi) {
          mma_f16(acc[mi][2 * q],     a[mi], b[q][0], b[q][1]);
          mma_f16(acc[mi][2 * q + 1], a[mi], b[q][2], b[q][3]);
        }
    }

    if (ch == 7) {
      const int n = nbase + (gc >> 3);
      __half* Cn = C + (long long)n * 262144;
#pragma unroll
      for (int mi = 0; mi < 4; ++mi) {
        int r0 = mt * 128 + wm + mi * 16 + grp;
#pragma unroll
        for (int ni = 0; ni < 8; ++ni) {
          int col = wn + ni * 8 + 2 * tg;
          __half2 h01 = __floats2half2_rn(acc[mi][ni][0], acc[mi][ni][1]);
          __half2 h23 = __floats2half2_rn(acc[mi][ni][2], acc[mi][ni][3]);
          *(uint32_t*)(Cn + (long long)r0 * 256 + col) = *(uint32_t*)&h01;
          *(uint32_t*)(Cn + (long long)(r0 + 8) * 256 + col) = *(uint32_t*)&h23;
#pragma unroll
          for (int q = 0; q < 4; ++q) acc[mi][ni][q] = 0.f;
        }
      }
    }
  }
}

// ================= GEMM2: out[n] = H12 . M1[n]^T =================
// CTA: 8 warps (2m x 4n), tile 128(m) x 256(n, full). 4-stage, K=1024.
#define STG2_H 15360   // (128 + 256) * PADH halves per stage

__global__ __launch_bounds__(256, 1) void tt_gemm2(
    const __half* __restrict__ A, const __half* __restrict__ Bbase,
    float* __restrict__ Cbase, const float* __restrict__ bias) {
  extern __shared__ __align__(16) __half smh[];
  const int t = threadIdx.x;
  const int lane = t & 31, wid = t >> 5;
  const int grp = lane >> 2, tg = lane & 3;
  const int mt = blockIdx.x;
  const int n = blockIdx.y;
  const int wm = (wid & 1) * 64, wn = (wid >> 1) * 64;
  const int K = 1024;

  const __half* Am = A + (long long)mt * 128 * K;
  const __half* Bn = Bbase + (long long)n * 262144;

  const int srow = t >> 2, sq = t & 3;
  const uint32_t base = smem_u32(smh);
  const uint32_t stA = base + (uint32_t)(srow * PADH + sq * 8) * 2u;
  const uint32_t stB = stA + (uint32_t)128 * PADH * 2u;

  uint32_t aOff[4];
#pragma unroll
  for (int mi = 0; mi < 4; ++mi)
    aOff[mi] = (uint32_t)((wm + mi * 16 + (lane & 15)) * PADH + (lane >> 4) * 8) * 2u;
  uint32_t bOff[4];
#pragma unroll
  for (int q = 0; q < 4; ++q)
    bOff[q] = (uint32_t)((wn + q * 16 + (lane & 7) + ((lane >> 4) << 3)) * PADH +
                         (((lane >> 3) & 1) << 3)) * 2u + (uint32_t)128 * PADH * 2u;

  float acc[4][8][4];
#pragma unroll
  for (int mi = 0; mi < 4; ++mi)
#pragma unroll
    for (int ni = 0; ni < 8; ++ni)
#pragma unroll
      for (int q = 0; q < 4; ++q) acc[mi][ni][q] = 0.f;

  const int nch = K >> 5;  // 32

#pragma unroll
  for (int pch = 0; pch < 3; ++pch) {
    const __half* ga = Am + pch * 32;
    const __half* gb = Bn + pch * 32;
    const uint32_t so = (uint32_t)pch * STG2_H * 2u;
#pragma unroll
    for (int rep = 0; rep < 2; ++rep)
      cp16(stA + so + rep * 64u * PADH * 2u, ga + (long long)(srow + rep * 64) * K + sq * 8);
#pragma unroll
    for (int rep = 0; rep < 4; ++rep)
      cp16(stB + so + rep * 64u * PADH * 2u, gb + (long long)(srow + rep * 64) * K + sq * 8);
    asm volatile("cp.async.commit_group;" ::: "memory");
  }

  for (int ch = 0; ch < nch; ++ch) {
    asm volatile("cp.async.wait_group 2;" ::: "memory");
    __syncthreads();

    if (ch + 3 < nch) {
      const __half* ga = Am + (ch + 3) * 32;
      const __half* gb = Bn + (ch + 3) * 32;
      const uint32_t so = (uint32_t)((ch + 3) & 3) * STG2_H * 2u;
#pragma unroll
      for (int rep = 0; rep < 2; ++rep)
        cp16(stA + so + rep * 64u * PADH * 2u, ga + (long long)(srow + rep * 64) * K + sq * 8);
#pragma unroll
      for (int rep = 0; rep < 4; ++rep)
        cp16(stB + so + rep * 64u * PADH * 2u, gb + (long long)(srow + rep * 64) * K + sq * 8);
    }
    asm volatile("cp.async.commit_group;" ::: "memory");

    const uint32_t sbase = base + (uint32_t)(ch & 3) * STG2_H * 2u;
#pragma unroll
    for (int sel = 0; sel < 2; ++sel) {
      const uint32_t ko = (uint32_t)sel * 32u;
      uint32_t a[4][4], b[4][4];
#pragma unroll
      for (int mi = 0; mi < 4; ++mi) ldsm_x4(a[mi], sbase + aOff[mi] + ko);
#pragma unroll
      for (int q = 0; q < 4; ++q) ldsm_x4(b[q], sbase + bOff[q] + ko);
#pragma unroll
      for (int q = 0; q < 4; ++q)
#pragma unroll
        for (int mi = 0; mi < 4; ++mi) {
          mma_f16(acc[mi][2 * q],     a[mi], b[q][0], b[q][1]);
          mma_f16(acc[mi][2 * q + 1], a[mi], b[q][2], b[q][3]);
        }
    }
  }

  float* Cn = Cbase + (long long)n * 65536;
#pragma unroll
  for (int mi = 0; mi < 4; ++mi) {
    int r0 = mt * 128 + wm + mi * 16 + grp;
#pragma unroll
    for (int ni = 0; ni < 8; ++ni) {
      int col = wn + ni * 8 + 2 * tg;
      float v0 = fmaxf(acc[mi][ni][0] + bias[r0 * 256 + col], 0.f);
      float v1 = fmaxf(acc[mi][ni][1] + bias[r0 * 256 + col + 1], 0.f);
      float v2 = fmaxf(acc[mi][ni][2] + bias[(r0 + 8) * 256 + col], 0.f);
      float v3 = fmaxf(acc[mi][ni][3] + bias[(r0 + 8) * 256 + col + 1], 0.f);
      *(float2*)(Cn + (long long)r0 * 256 + col) = make_float2(v0, v1);
      *(float2*)(Cn + (long long)(r0 + 8) * 256 + col) = make_float2(v2, v3);
    }
  }
}

// ---------------- launch ----------------
extern "C" void kernel_launch(void* const* d_in, const int* in_sizes, int n_in,
                              void* d_out, int out_size) {
  const float* x    = (const float*)d_in[0];
  const float* G1   = (const float*)d_in[1];
  const float* G2   = (const float*)d_in[2];
  const float* G3   = (const float*)d_in[3];
  const float* G4   = (const float*)d_in[4];
  const float* bias = (const float*)d_in[5];
  float* out = (float*)d_out;
  const int nb = in_sizes[0] / 65536;

  __half *pH34, *pH12, *pM1, *pXr;
  cudaGetSymbolAddress((void**)&pH34, g_H34);
  cudaGetSymbolAddress((void**)&pH12, g_H12);
  cudaGetSymbolAddress((void**)&pM1, g_M1);
  cudaGetSymbolAddress((void**)&pXr, g_Xr);

  const int smem1 = (A_RES_H + 4 * B1_STG_H) * 2;  // 149504 B
  const int smem2 = 4 * STG2_H * 2;                // 122880 B
  cudaFuncSetAttribute(tt_gemm1, cudaFuncAttributeMaxDynamicSharedMemorySize, smem1);
  cudaFuncSetAttribute(tt_gemm2, cudaFuncAttributeMaxDynamicSharedMemorySize, smem2);

  prep_h34<<<1024, 256>>>(G3, G4);
  prep_h12<<<1024, 256>>>(G1, G2);
  round_x<<<in_sizes[0] / 1024, 256>>>(x);

  // GEMM1: grid (8 mtiles, nb/8 sample-groups)
  tt_gemm1<<<dim3(8, nb / NGRP), 256, smem1>>>(pH34, pXr, pM1);
  // GEMM2: grid (2 mtiles, nb)
  tt_gemm2<<<dim3(2, nb), 256, smem2>>>(pH12, pM1, out, bias);
}

// round 12
// speedup vs baseline: 1.1375x; 1.1375x over previous
#include <cuda_runtime.h>
#include <cuda_fp16.h>
#include <cstdint>

// TT layer via merged-core fp16 mma.sync GEMMs (m16n8k16, fp32 accumulate).
// Round 12: pair-granularity (k64) sync/wait in both GEMMs; GEMM2 streams
// 4 samples per CTA (continuous pipeline). GEMM1 keeps resident A + 8-sample
// streaming. CTA 128x128, 8 warps x 32x64, 2 CTA/SM.
// out[n,ab,cd] = relu( sum H12[ab,(s,ij)] x[n,ij,kl] H34[(cd,s),kl] + bias )
// GEMM1 per n: M1[cds, ij] = H34 . Xr[n]^T   M=1024 N=256 K=256
// GEMM2 per n: out[ab, cd] = H12 . M1[n]^T   M=256  N=256 K=1024 (+bias,relu)

__device__ __half g_H34[262144];
__device__ __half g_H12[262144];
__device__ __half g_Xr[67108864];   // RNE-rounded x (128 MB)
__device__ __half g_M1[268435456];  // M1 fp16 (512 MB)

__device__ __forceinline__ uint32_t smem_u32(const void* p) {
  uint32_t a;
  asm("{ .reg .u64 t; cvta.to.shared.u64 t, %1; cvt.u32.u64 %0, t; }" : "=r"(a) : "l"(p));
  return a;
}
__device__ __forceinline__ void cp16(uint32_t s, const __half* g) {
  asm volatile("cp.async.cg.shared.global [%0], [%1], 16;" :: "r"(s), "l"(g));
}
__device__ __forceinline__ void mma_f16(float* c, const uint32_t* a, uint32_t b0, uint32_t b1) {
  asm volatile(
      "mma.sync.aligned.m16n8k16.row.col.f32.f16.f16.f32 "
      "{%0,%1,%2,%3}, {%4,%5,%6,%7}, {%8,%9}, {%0,%1,%2,%3};"
      : "+f"(c[0]), "+f"(c[1]), "+f"(c[2]), "+f"(c[3])
      : "r"(a[0]), "r"(a[1]), "r"(a[2]), "r"(a[3]), "r"(b0), "r"(b1));
}
__device__ __forceinline__ void ldsm_x4(uint32_t* r, uint32_t addr) {
  asm volatile("ldmatrix.sync.aligned.m8n8.x4.shared.b16 {%0,%1,%2,%3}, [%4];"
               : "=r"(r[0]), "=r"(r[1]), "=r"(r[2]), "=r"(r[3]) : "r"(addr));
}

// ---------------- precompute (fp32 math, RNE fp16 store) ----------------
__global__ void prep_h34(const float* __restrict__ G3, const float* __restrict__ G4) {
  int e = blockIdx.x * 256 + threadIdx.x;
  int col = e & 255, row = e >> 8;
  int s = row & 3, cd = row >> 2;
  int c = cd >> 4, d = cd & 15, k = col >> 4, l = col & 15;
  float acc = 0.f;
#pragma unroll
  for (int tt = 0; tt < 4; ++tt)
    acc += G3[((c * 16 + k) * 4 + s) * 4 + tt] * G4[(d * 16 + l) * 4 + tt];
  g_H34[e] = __float2half_rn(acc);
}
__global__ void prep_h12(const float* __restrict__ G1, const float* __restrict__ G2) {
  int e = blockIdx.x * 256 + threadIdx.x;
  int ab = e >> 10, k = e & 1023;
  int s = k >> 8, ij = k & 255;
  int a = ab >> 4, b = ab & 15, i = ij >> 4, j = ij & 15;
  float acc = 0.f;
#pragma unroll
  for (int r = 0; r < 4; ++r)
    acc += G1[(a * 16 + i) * 4 + r] * G2[((b * 16 + j) * 4 + r) * 4 + s];
  g_H12[e] = __float2half_rn(acc);
}
__global__ __launch_bounds__(256) void round_x(const float* __restrict__ x) {
  size_t idx = (size_t)blockIdx.x * 256 + threadIdx.x;
  float4 v = *(const float4*)(x + idx * 4);
  __half2 h0 = __floats2half2_rn(v.x, v.y);
  __half2 h1 = __floats2half2_rn(v.z, v.w);
  uint2 o = { *(uint32_t*)&h0, *(uint32_t*)&h1 };
  *(uint2*)(g_Xr + idx * 4) = o;
}

#define PADH 40
#define PADA 264          // resident A row stride (256 + 8 halves)
#define A_RES_H 33792     // 128 * PADA
#define B_STG_H 5120      // GEMM1 B stage: 128 rows * PADH
#define NGRP 8            // samples per GEMM1 CTA
#define NGRP2 4           // samples per GEMM2 CTA

// ================= GEMM1: M1[n] = H34_mtile . Xr[n]^T =================
// CTA 128(m) x 128(n), A resident; 8*NGRP chunks, pair-sync protocol.
__global__ __launch_bounds__(256, 2) void tt_gemm1(
    const __half* __restrict__ A, const __half* __restrict__ B,
    __half* __restrict__ C) {
  extern __shared__ __align__(16) __half smh[];
  const int t = threadIdx.x;
  const int lane = t & 31, wid = t >> 5;
  const int grp = lane >> 2, tg = lane & 3;
  const int nt = blockIdx.x & 1, mt = blockIdx.x >> 1;
  const int nbase = blockIdx.y * NGRP;
  const int wm = (wid & 3) * 32, wn = (wid >> 2) * 64;

  const uint32_t base = smem_u32(smh);
  const uint32_t bbase = base + A_RES_H * 2u;

  // resident A tile: 128 rows x 256 halves
  {
    const __half* Am = A + (long long)mt * 128 * 256;
#pragma unroll
    for (int rep = 0; rep < 16; ++rep) {
      int idx = rep * 256 + t;
      int row = idx >> 5, seg = idx & 31;
      cp16(base + (uint32_t)(row * PADA + seg * 8) * 2u, Am + row * 256 + seg * 8);
    }
  }

  uint32_t aOff[2];
#pragma unroll
  for (int mi = 0; mi < 2; ++mi)
    aOff[mi] = (uint32_t)((wm + mi * 16 + (lane & 15)) * PADA + (lane >> 4) * 8) * 2u;
  uint32_t bOff[4];
#pragma unroll
  for (int q = 0; q < 4; ++q)
    bOff[q] = (uint32_t)((wn + q * 16 + (lane & 7) + ((lane >> 4) << 3)) * PADH +
                         (((lane >> 3) & 1) << 3)) * 2u;

  // B loader: chunk c -> sample nbase + (c>>3), k-chunk (c&7), slot c&3.
  const int srow = t >> 2, sq = t & 3;
  const uint32_t stB = bbase + (uint32_t)(srow * PADH + sq * 8) * 2u;
  const __half* Bnt = B + (long long)nt * 128 * 256;

  // prologue: pair 0 (chunks 0,1) + A in ONE commit group
#pragma unroll
  for (int c = 0; c < 2; ++c) {
    const __half* gb = Bnt + (long long)nbase * 65536 + c * 32;
    const uint32_t so = (uint32_t)c * B_STG_H * 2u;
#pragma unroll
    for (int rep = 0; rep < 2; ++rep)
      cp16(stB + so + rep * 64u * PADH * 2u, gb + (long long)(srow + rep * 64) * 256 + sq * 8);
  }
  asm volatile("cp.async.commit_group;" ::: "memory");

  float acc[2][8][4];
#pragma unroll
  for (int mi = 0; mi < 2; ++mi)
#pragma unroll
    for (int ni = 0; ni < 8; ++ni)
#pragma unroll
      for (int q = 0; q < 4; ++q) acc[mi][ni][q] = 0.f;

  const int NC = 8 * NGRP;
  for (int p = 0; p < NC / 2; ++p) {
    asm volatile("cp.async.wait_group 0;" ::: "memory");
    __syncthreads();

    // prefetch pair p+1 (slots freed at pair p-1)
    if (2 * p + 2 < NC) {
#pragma unroll
      for (int e = 0; e < 2; ++e) {
        int c = 2 * p + 2 + e;
        const __half* gb = Bnt + (long long)(nbase + (c >> 3)) * 65536 + (c & 7) * 32;
        const uint32_t so = (uint32_t)(c & 3) * B_STG_H * 2u;
#pragma unroll
        for (int rep = 0; rep < 2; ++rep)
          cp16(stB + so + rep * 64u * PADH * 2u,
               gb + (long long)(srow + rep * 64) * 256 + sq * 8);
      }
    }
    asm volatile("cp.async.commit_group;" ::: "memory");

    // compute both chunks of pair p
#pragma unroll
    for (int e = 0; e < 2; ++e) {
      const int c = 2 * p + e;
      const uint32_t sa = base + (uint32_t)(c & 7) * 64u;  // +32 halves per k-chunk
      const uint32_t sb = bbase + (uint32_t)(c & 3) * B_STG_H * 2u;
#pragma unroll
      for (int sel = 0; sel < 2; ++sel) {
        const uint32_t ko = (uint32_t)sel * 32u;
        uint32_t a[2][4], b[4][4];
        ldsm_x4(a[0], sa + aOff[0] + ko);
        ldsm_x4(a[1], sa + aOff[1] + ko);
#pragma unroll
        for (int q = 0; q < 4; ++q) ldsm_x4(b[q], sb + bOff[q] + ko);
#pragma unroll
        for (int q = 0; q < 4; ++q)
#pragma unroll
          for (int mi = 0; mi < 2; ++mi) {
            mma_f16(acc[mi][2 * q],     a[mi], b[q][0], b[q][1]);
            mma_f16(acc[mi][2 * q + 1], a[mi], b[q][2], b[q][3]);
          }
      }
    }

    if ((p & 3) == 3) {  // sample boundary (8 chunks = 4 pairs)
      const int n = nbase + (p >> 2);
      __half* Cn = C + (long long)n * 262144;
#pragma unroll
      for (int mi = 0; mi < 2; ++mi) {
        int r0 = mt * 128 + wm + mi * 16 + grp;
#pragma unroll
        for (int ni = 0; ni < 8; ++ni) {
          int col = nt * 128 + wn + ni * 8 + 2 * tg;
          __half2 h01 = __floats2half2_rn(acc[mi][ni][0], acc[mi][ni][1]);
          __half2 h23 = __floats2half2_rn(acc[mi][ni][2], acc[mi][ni][3]);
          *(uint32_t*)(Cn + (long long)r0 * 256 + col) = *(uint32_t*)&h01;
          *(uint32_t*)(Cn + (long long)(r0 + 8) * 256 + col) = *(uint32_t*)&h23;
#pragma unroll
          for (int q = 0; q < 4; ++q) acc[mi][ni][q] = 0.f;
        }
      }
    }
  }
}

// ================= GEMM2: out[n] = H12 . M1[n]^T =================
// CTA 128x128, NGRP2 samples streamed, pair-sync protocol, K=1024.
#define STG2_H 10240   // halves per stage (A 128 rows + B 128 rows, PADH)

__global__ __launch_bounds__(256, 2) void tt_gemm2(
    const __half* __restrict__ A, const __half* __restrict__ Bbase,
    float* __restrict__ Cbase, const float* __restrict__ bias) {
  extern __shared__ __align__(16) __half smh[];
  const int t = threadIdx.x;
  const int lane = t & 31, wid = t >> 5;
  const int grp = lane >> 2, tg = lane & 3;
  const int nt = blockIdx.x & 1, mt = blockIdx.x >> 1;
  const int nbase = blockIdx.y * NGRP2;
  const int wm = (wid & 3) * 32, wn = (wid >> 2) * 64;
  const int K = 1024;

  const __half* Am = A + (long long)mt * 128 * K;
  const __half* Bb = Bbase + (long long)nt * 128 * K;

  const int srow = t >> 2, sq = t & 3;
  const uint32_t base = smem_u32(smh);
  const uint32_t stA = base + (uint32_t)(srow * PADH + sq * 8) * 2u;
  const uint32_t stB = stA + (uint32_t)128 * PADH * 2u;

  uint32_t aOff[2];
#pragma unroll
  for (int mi = 0; mi < 2; ++mi)
    aOff[mi] = (uint32_t)((wm + mi * 16 + (lane & 15)) * PADH + (lane >> 4) * 8) * 2u;
  uint32_t bOff[4];
#pragma unroll
  for (int q = 0; q < 4; ++q)
    bOff[q] = (uint32_t)((wn + q * 16 + (lane & 7) + ((lane >> 4) << 3)) * PADH +
                         (((lane >> 3) & 1) << 3)) * 2u + (uint32_t)128 * PADH * 2u;

  float acc[2][8][4];
#pragma unroll
  for (int mi = 0; mi < 2; ++mi)
#pragma unroll
    for (int ni = 0; ni < 8; ++ni)
#pragma unroll
      for (int q = 0; q < 4; ++q) acc[mi][ni][q] = 0.f;

  const int NC = 32 * NGRP2;  // 128 chunks

  // prologue: pair 0 (chunks 0,1 of sample nbase)
#pragma unroll
  for (int c = 0; c < 2; ++c) {
    const uint32_t so = (uint32_t)c * STG2_H * 2u;
    const __half* ga = Am + c * 32;
    const __half* gb = Bb + (long long)nbase * 262144 + c * 32;
#pragma unroll
    for (int rep = 0; rep < 2; ++rep) {
      cp16(stA + so + rep * 64u * PADH * 2u, ga + (long long)(srow + rep * 64) * K + sq * 8);
      cp16(stB + so + rep * 64u * PADH * 2u, gb + (long long)(srow + rep * 64) * K + sq * 8);
    }
  }
  asm volatile("cp.async.commit_group;" ::: "memory");

  for (int p = 0; p < NC / 2; ++p) {
    asm volatile("cp.async.wait_group 0;" ::: "memory");
    __syncthreads();

    if (2 * p + 2 < NC) {
#pragma unroll
      for (int e = 0; e < 2; ++e) {
        int c = 2 * p + 2 + e;
        const uint32_t so = (uint32_t)(c & 3) * STG2_H * 2u;
        const __half* ga = Am + (c & 31) * 32;
        const __half* gb = Bb + (long long)(nbase + (c >> 5)) * 262144 + (c & 31) * 32;
#pragma unroll
        for (int rep = 0; rep < 2; ++rep) {
          cp16(stA + so + rep * 64u * PADH * 2u, ga + (long long)(srow + rep * 64) * K + sq * 8);
          cp16(stB + so + rep * 64u * PADH * 2u, gb + (long long)(srow + rep * 64) * K + sq * 8);
        }
      }
    }
    asm volatile("cp.async.commit_group;" ::: "memory");

#pragma unroll
    for (int e = 0; e < 2; ++e) {
      const int c = 2 * p + e;
      const uint32_t sbase = base + (uint32_t)(c & 3) * STG2_H * 2u;
#pragma unroll
      for (int sel = 0; sel < 2; ++sel) {
        const uint32_t ko = (uint32_t)sel * 32u;
        uint32_t a[2][4], b[4][4];
        ldsm_x4(a[0], sbase + aOff[0] + ko);
        ldsm_x4(a[1], sbase + aOff[1] + ko);
#pragma unroll
        for (int q = 0; q < 4; ++q) ldsm_x4(b[q], sbase + bOff[q] + ko);
#pragma unroll
        for (int q = 0; q < 4; ++q)
#pragma unroll
          for (int mi = 0; mi < 2; ++mi) {
            mma_f16(acc[mi][2 * q],     a[mi], b[q][0], b[q][1]);
            mma_f16(acc[mi][2 * q + 1], a[mi], b[q][2], b[q][3]);
          }
      }
    }

    if ((p & 15) == 15) {  // sample boundary (32 chunks = 16 pairs)
      const int n = nbase + (p >> 4);
      float* Cn = Cbase + (long long)n * 65536;
#pragma unroll
      for (int mi = 0; mi < 2; ++mi) {
        int r0 = mt * 128 + wm + mi * 16 + grp;
#pragma unroll
        for (int ni = 0; ni < 8; ++ni) {
          int col = nt * 128 + wn + ni * 8 + 2 * tg;
          float v0 = fmaxf(acc[mi][ni][0] + bias[r0 * 256 + col], 0.f);
          float v1 = fmaxf(acc[mi][ni][1] + bias[r0 * 256 + col + 1], 0.f);
          float v2 = fmaxf(acc[mi][ni][2] + bias[(r0 + 8) * 256 + col], 0.f);
          float v3 = fmaxf(acc[mi][ni][3] + bias[(r0 + 8) * 256 + col + 1], 0.f);
          *(float2*)(Cn + (long long)r0 * 256 + col) = make_float2(v0, v1);
          *(float2*)(Cn + (long long)(r0 + 8) * 256 + col) = make_float2(v2, v3);
#pragma unroll
          for (int q = 0; q < 4; ++q) acc[mi][ni][q] = 0.f;
        }
      }
    }
  }
}

// ---------------- launch ----------------
extern "C" void kernel_launch(void* const* d_in, const int* in_sizes, int n_in,
                              void* d_out, int out_size) {
  const float* x    = (const float*)d_in[0];
  const float* G1   = (const float*)d_in[1];
  const float* G2   = (const float*)d_in[2];
  const float* G3   = (const float*)d_in[3];
  const float* G4   = (const float*)d_in[4];
  const float* bias = (const float*)d_in[5];
  float* out = (float*)d_out;
  const int nb = in_sizes[0] / 65536;

  __half *pH34, *pH12, *pM1, *pXr;
  cudaGetSymbolAddress((void**)&pH34, g_H34);
  cudaGetSymbolAddress((void**)&pH12, g_H12);
  cudaGetSymbolAddress((void**)&pM1, g_M1);
  cudaGetSymbolAddress((void**)&pXr, g_Xr);

  const int smem1 = (A_RES_H + 4 * B_STG_H) * 2;  // 108544 B
  const int smem2 = 4 * STG2_H * 2;               // 81920 B
  cudaFuncSetAttribute(tt_gemm1, cudaFuncAttributeMaxDynamicSharedMemorySize, smem1);
  cudaFuncSetAttribute(tt_gemm2, cudaFuncAttributeMaxDynamicSharedMemorySize, smem2);

  prep_h34<<<1024, 256>>>(G3, G4);
  prep_h12<<<1024, 256>>>(G1, G2);
  round_x<<<in_sizes[0] / 1024, 256>>>(x);

  // GEMM1: grid (8 mtiles x 2 ntiles, nb/NGRP sample-groups)
  tt_gemm1<<<dim3(16, nb / NGRP), 256, smem1>>>(pH34, pXr, pM1);
  // GEMM2: grid (2 mtiles x 2 ntiles, nb/NGRP2 sample-groups)
  tt_gemm2<<<dim3(4, nb / NGRP2), 256, smem2>>>(pH12, pM1, out, bias);
}

// round 13
// speedup vs baseline: 1.1870x; 1.0436x over previous
#include <cuda_runtime.h>
#include <cuda_fp16.h>
#include <cstdint>

// TT layer via merged-core fp16 mma.sync GEMMs (m16n8k16, fp32 accumulate).
// Round 13: r10's proven per-chunk wait_group-2 protocol in BOTH kernels;
// GEMM1 resident-A + 8-sample streaming (unchanged from r10); GEMM2 now also
// streams 4 samples per CTA with a continuous pipeline.
// out[n,ab,cd] = relu( sum H12[ab,(s,ij)] x[n,ij,kl] H34[(cd,s),kl] + bias )
// GEMM1 per n: M1[cds, ij] = H34 . Xr[n]^T   M=1024 N=256 K=256
// GEMM2 per n: out[ab, cd] = H12 . M1[n]^T   M=256  N=256 K=1024 (+bias,relu)

__device__ __half g_H34[262144];
__device__ __half g_H12[262144];
__device__ __half g_Xr[67108864];   // RNE-rounded x (128 MB)
__device__ __half g_M1[268435456];  // M1 fp16 (512 MB)

__device__ __forceinline__ uint32_t smem_u32(const void* p) {
  uint32_t a;
  asm("{ .reg .u64 t; cvta.to.shared.u64 t, %1; cvt.u32.u64 %0, t; }" : "=r"(a) : "l"(p));
  return a;
}
__device__ __forceinline__ void cp16(uint32_t s, const __half* g) {
  asm volatile("cp.async.cg.shared.global [%0], [%1], 16;" :: "r"(s), "l"(g));
}
__device__ __forceinline__ void mma_f16(float* c, const uint32_t* a, uint32_t b0, uint32_t b1) {
  asm volatile(
      "mma.sync.aligned.m16n8k16.row.col.f32.f16.f16.f32 "
      "{%0,%1,%2,%3}, {%4,%5,%6,%7}, {%8,%9}, {%0,%1,%2,%3};"
      : "+f"(c[0]), "+f"(c[1]), "+f"(c[2]), "+f"(c[3])
      : "r"(a[0]), "r"(a[1]), "r"(a[2]), "r"(a[3]), "r"(b0), "r"(b1));
}
__device__ __forceinline__ void ldsm_x4(uint32_t* r, uint32_t addr) {
  asm volatile("ldmatrix.sync.aligned.m8n8.x4.shared.b16 {%0,%1,%2,%3}, [%4];"
               : "=r"(r[0]), "=r"(r[1]), "=r"(r[2]), "=r"(r[3]) : "r"(addr));
}

// ---------------- precompute (fp32 math, RNE fp16 store) ----------------
__global__ void prep_h34(const float* __restrict__ G3, const float* __restrict__ G4) {
  int e = blockIdx.x * 256 + threadIdx.x;
  int col = e & 255, row = e >> 8;
  int s = row & 3, cd = row >> 2;
  int c = cd >> 4, d = cd & 15, k = col >> 4, l = col & 15;
  float acc = 0.f;
#pragma unroll
  for (int tt = 0; tt < 4; ++tt)
    acc += G3[((c * 16 + k) * 4 + s) * 4 + tt] * G4[(d * 16 + l) * 4 + tt];
  g_H34[e] = __float2half_rn(acc);
}
__global__ void prep_h12(const float* __restrict__ G1, const float* __restrict__ G2) {
  int e = blockIdx.x * 256 + threadIdx.x;
  int ab = e >> 10, k = e & 1023;
  int s = k >> 8, ij = k & 255;
  int a = ab >> 4, b = ab & 15, i = ij >> 4, j = ij & 15;
  float acc = 0.f;
#pragma unroll
  for (int r = 0; r < 4; ++r)
    acc += G1[(a * 16 + i) * 4 + r] * G2[((b * 16 + j) * 4 + r) * 4 + s];
  g_H12[e] = __float2half_rn(acc);
}
__global__ __launch_bounds__(256) void round_x(const float* __restrict__ x) {
  size_t idx = (size_t)blockIdx.x * 256 + threadIdx.x;
  float4 v = *(const float4*)(x + idx * 4);
  __half2 h0 = __floats2half2_rn(v.x, v.y);
  __half2 h1 = __floats2half2_rn(v.z, v.w);
  uint2 o = { *(uint32_t*)&h0, *(uint32_t*)&h1 };
  *(uint2*)(g_Xr + idx * 4) = o;
}

#define PADH 40
#define PADA 264          // resident A row stride in halves (256 + 8)
#define A_RES_H 33792     // 128 * PADA
#define B_STG_H 5120      // GEMM1 B stage: 128 rows * PADH
#define NGRP 8            // samples per GEMM1 CTA
#define NGRP2 4           // samples per GEMM2 CTA

// ============ GEMM1: M1[n] = H34_mtile . Xr[n]^T, A resident ============
// CTA: 8 warps (4m x 2n), tile 128 x 128. K=256 = 8 chunks; NGRP samples
// streamed with a continuous 4-stage B pipeline, wait_group 2.
__global__ __launch_bounds__(256, 2) void tt_gemm1(
    const __half* __restrict__ A, const __half* __restrict__ B,
    __half* __restrict__ C) {
  extern __shared__ __align__(16) __half smh[];
  const int t = threadIdx.x;
  const int lane = t & 31, wid = t >> 5;
  const int grp = lane >> 2, tg = lane & 3;
  const int nt = blockIdx.x & 1, mt = blockIdx.x >> 1;
  const int nbase = blockIdx.y * NGRP;
  const int wm = (wid & 3) * 32, wn = (wid >> 2) * 64;

  const uint32_t base = smem_u32(smh);
  const uint32_t bbase = base + A_RES_H * 2u;

  // resident A tile: 128 rows x 256 halves
  {
    const __half* Am = A + (long long)mt * 128 * 256;
#pragma unroll
    for (int rep = 0; rep < 16; ++rep) {
      int idx = rep * 256 + t;
      int row = idx >> 5, seg = idx & 31;
      cp16(base + (uint32_t)(row * PADA + seg * 8) * 2u, Am + row * 256 + seg * 8);
    }
    asm volatile("cp.async.commit_group;" ::: "memory");
  }

  uint32_t aOff[2];
#pragma unroll
  for (int mi = 0; mi < 2; ++mi)
    aOff[mi] = (uint32_t)((wm + mi * 16 + (lane & 15)) * PADA + (lane >> 4) * 8) * 2u;
  uint32_t bOff[4];
#pragma unroll
  for (int q = 0; q < 4; ++q)
    bOff[q] = (uint32_t)((wn + q * 16 + (lane & 7) + ((lane >> 4) << 3)) * PADH +
                         (((lane >> 3) & 1) << 3)) * 2u;

  const int srow = t >> 2, sq = t & 3;
  const uint32_t stB = bbase + (uint32_t)(srow * PADH + sq * 8) * 2u;
  const __half* Bnt = B + (long long)nt * 128 * 256;

  // prologue: B chunks 0,1,2 of sample nbase
#pragma unroll
  for (int pch = 0; pch < 3; ++pch) {
    const __half* gb = Bnt + (long long)nbase * 65536 + pch * 32;
    const uint32_t so = (uint32_t)pch * B_STG_H * 2u;
#pragma unroll
    for (int rep = 0; rep < 2; ++rep)
      cp16(stB + so + rep * 64u * PADH * 2u, gb + (long long)(srow + rep * 64) * 256 + sq * 8);
    asm volatile("cp.async.commit_group;" ::: "memory");
  }

  float acc[2][8][4];
#pragma unroll
  for (int mi = 0; mi < 2; ++mi)
#pragma unroll
    for (int ni = 0; ni < 8; ++ni)
#pragma unroll
      for (int q = 0; q < 4; ++q) acc[mi][ni][q] = 0.f;

  for (int gc = 0; gc < 8 * NGRP; ++gc) {
    const int ch = gc & 7;
    asm volatile("cp.async.wait_group 2;" ::: "memory");
    __syncthreads();

    if (gc + 3 < 8 * NGRP) {
      int g2 = gc + 3;
      const __half* gb = Bnt + (long long)(nbase + (g2 >> 3)) * 65536 + (g2 & 7) * 32;
      const uint32_t so = (uint32_t)(g2 & 3) * B_STG_H * 2u;
#pragma unroll
      for (int rep = 0; rep < 2; ++rep)
        cp16(stB + so + rep * 64u * PADH * 2u, gb + (long long)(srow + rep * 64) * 256 + sq * 8);
    }
    asm volatile("cp.async.commit_group;" ::: "memory");

    const uint32_t sa = base + (uint32_t)ch * 64u;  // +32 halves per k-chunk
    const uint32_t sb = bbase + (uint32_t)(gc & 3) * B_STG_H * 2u;
#pragma unroll
    for (int sel = 0; sel < 2; ++sel) {
      const uint32_t ko = (uint32_t)sel * 32u;
      uint32_t a[2][4], b[4][4];
      ldsm_x4(a[0], sa + aOff[0] + ko);
      ldsm_x4(a[1], sa + aOff[1] + ko);
#pragma unroll
      for (int q = 0; q < 4; ++q) ldsm_x4(b[q], sb + bOff[q] + ko);
#pragma unroll
      for (int q = 0; q < 4; ++q)
#pragma unroll
        for (int mi = 0; mi < 2; ++mi) {
          mma_f16(acc[mi][2 * q],     a[mi], b[q][0], b[q][1]);
          mma_f16(acc[mi][2 * q + 1], a[mi], b[q][2], b[q][3]);
        }
    }

    if (ch == 7) {  // sample epilogue
      const int n = nbase + (gc >> 3);
      __half* Cn = C + (long long)n * 262144;
#pragma unroll
      for (int mi = 0; mi < 2; ++mi) {
        int r0 = mt * 128 + wm + mi * 16 + grp;
#pragma unroll
        for (int ni = 0; ni < 8; ++ni) {
          int col = nt * 128 + wn + ni * 8 + 2 * tg;
          __half2 h01 = __floats2half2_rn(acc[mi][ni][0], acc[mi][ni][1]);
          __half2 h23 = __floats2half2_rn(acc[mi][ni][2], acc[mi][ni][3]);
          *(uint32_t*)(Cn + (long long)r0 * 256 + col) = *(uint32_t*)&h01;
          *(uint32_t*)(Cn + (long long)(r0 + 8) * 256 + col) = *(uint32_t*)&h23;
#pragma unroll
          for (int q = 0; q < 4; ++q) acc[mi][ni][q] = 0.f;
        }
      }
    }
  }
}

// ============ GEMM2: out[n] = H12 . M1[n]^T, sample streaming ============
// CTA 128x128; NGRP2 samples, 32*NGRP2 continuous chunks, 4-stage,
// wait_group 2 (r10 protocol). Epilogue at 32-chunk boundaries.
#define STG2_H 10240   // halves per stage (A 128 rows + B 128 rows, PADH)

__global__ __launch_bounds__(256, 2) void tt_gemm2(
    const __half* __restrict__ A, const __half* __restrict__ Bbase,
    float* __restrict__ Cbase, const float* __restrict__ bias) {
  extern __shared__ __align__(16) __half smh[];
  const int t = threadIdx.x;
  const int lane = t & 31, wid = t >> 5;
  const int grp = lane >> 2, tg = lane & 3;
  const int nt = blockIdx.x & 1, mt = blockIdx.x >> 1;
  const int nbase = blockIdx.y * NGRP2;
  const int wm = (wid & 3) * 32, wn = (wid >> 2) * 64;
  const int K = 1024;

  const __half* Am = A + (long long)mt * 128 * K;
  const __half* Bb = Bbase + (long long)nt * 128 * K;

  const int srow = t >> 2, sq = t & 3;
  const uint32_t base = smem_u32(smh);
  const uint32_t stA = base + (uint32_t)(srow * PADH + sq * 8) * 2u;
  const uint32_t stB = stA + (uint32_t)128 * PADH * 2u;

  uint32_t aOff[2];
#pragma unroll
  for (int mi = 0; mi < 2; ++mi)
    aOff[mi] = (uint32_t)((wm + mi * 16 + (lane & 15)) * PADH + (lane >> 4) * 8) * 2u;
  uint32_t bOff[4];
#pragma unroll
  for (int q = 0; q < 4; ++q)
    bOff[q] = (uint32_t)((wn + q * 16 + (lane & 7) + ((lane >> 4) << 3)) * PADH +
                         (((lane >> 3) & 1) << 3)) * 2u + (uint32_t)128 * PADH * 2u;

  float acc[2][8][4];
#pragma unroll
  for (int mi = 0; mi < 2; ++mi)
#pragma unroll
    for (int ni = 0; ni < 8; ++ni)
#pragma unroll
      for (int q = 0; q < 4; ++q) acc[mi][ni][q] = 0.f;

  const int NC = 32 * NGRP2;  // 128 chunks

  // prologue: chunks 0,1,2 of sample nbase
#pragma unroll
  for (int pch = 0; pch < 3; ++pch) {
    const __half* ga = Am + pch * 32;
    const __half* gb = Bb + (long long)nbase * 262144 + pch * 32;
    const uint32_t so = (uint32_t)pch * STG2_H * 2u;
#pragma unroll
    for (int rep = 0; rep < 2; ++rep) {
      cp16(stA + so + rep * 64u * PADH * 2u, ga + (long long)(srow + rep * 64) * K + sq * 8);
      cp16(stB + so + rep * 64u * PADH * 2u, gb + (long long)(srow + rep * 64) * K + sq * 8);
    }
    asm volatile("cp.async.commit_group;" ::: "memory");
  }

  for (int gc = 0; gc < NC; ++gc) {
    asm volatile("cp.async.wait_group 2;" ::: "memory");
    __syncthreads();

    if (gc + 3 < NC) {
      int g2 = gc + 3;
      const __half* ga = Am + (g2 & 31) * 32;
      const __half* gb = Bb + (long long)(nbase + (g2 >> 5)) * 262144 + (g2 & 31) * 32;
      const uint32_t so = (uint32_t)(g2 & 3) * STG2_H * 2u;
#pragma unroll
      for (int rep = 0; rep < 2; ++rep) {
        cp16(stA + so + rep * 64u * PADH * 2u, ga + (long long)(srow + rep * 64) * K + sq * 8);
        cp16(stB + so + rep * 64u * PADH * 2u, gb + (long long)(srow + rep * 64) * K + sq * 8);
      }
    }
    asm volatile("cp.async.commit_group;" ::: "memory");

    const uint32_t sbase = base + (uint32_t)(gc & 3) * STG2_H * 2u;
#pragma unroll
    for (int sel = 0; sel < 2; ++sel) {
      const uint32_t ko = (uint32_t)sel * 32u;
      uint32_t a[2][4], b[4][4];
      ldsm_x4(a[0], sbase + aOff[0] + ko);
      ldsm_x4(a[1], sbase + aOff[1] + ko);
#pragma unroll
      for (int q = 0; q < 4; ++q) ldsm_x4(b[q], sbase + bOff[q] + ko);
#pragma unroll
      for (int q = 0; q < 4; ++q)
#pragma unroll
        for (int mi = 0; mi < 2; ++mi) {
          mma_f16(acc[mi][2 * q],     a[mi], b[q][0], b[q][1]);
          mma_f16(acc[mi][2 * q + 1], a[mi], b[q][2], b[q][3]);
        }
    }

    if ((gc & 31) == 31) {  // sample epilogue
      const int n = nbase + (gc >> 5);
      float* Cn = Cbase + (long long)n * 65536;
#pragma unroll
      for (int mi = 0; mi < 2; ++mi) {
        int r0 = mt * 128 + wm + mi * 16 + grp;
#pragma unroll
        for (int ni = 0; ni < 8; ++ni) {
          int col = nt * 128 + wn + ni * 8 + 2 * tg;
          float v0 = fmaxf(acc[mi][ni][0] + bias[r0 * 256 + col], 0.f);
          float v1 = fmaxf(acc[mi][ni][1] + bias[r0 * 256 + col + 1], 0.f);
          float v2 = fmaxf(acc[mi][ni][2] + bias[(r0 + 8) * 256 + col], 0.f);
          float v3 = fmaxf(acc[mi][ni][3] + bias[(r0 + 8) * 256 + col + 1], 0.f);
          *(float2*)(Cn + (long long)r0 * 256 + col) = make_float2(v0, v1);
          *(float2*)(Cn + (long long)(r0 + 8) * 256 + col) = make_float2(v2, v3);
#pragma unroll
          for (int q = 0; q < 4; ++q) acc[mi][ni][q] = 0.f;
        }
      }
    }
  }
}

// ---------------- launch ----------------
extern "C" void kernel_launch(void* const* d_in, const int* in_sizes, int n_in,
                              void* d_out, int out_size) {
  const float* x    = (const float*)d_in[0];
  const float* G1   = (const float*)d_in[1];
  const float* G2   = (const float*)d_in[2];
  const float* G3   = (const float*)d_in[3];
  const float* G4   = (const float*)d_in[4];
  const float* bias = (const float*)d_in[5];
  float* out = (float*)d_out;
  const int nb = in_sizes[0] / 65536;

  __half *pH34, *pH12, *pM1, *pXr;
  cudaGetSymbolAddress((void**)&pH34, g_H34);
  cudaGetSymbolAddress((void**)&pH12, g_H12);
  cudaGetSymbolAddress((void**)&pM1, g_M1);
  cudaGetSymbolAddress((void**)&pXr, g_Xr);

  const int smem1 = (A_RES_H + 4 * B_STG_H) * 2;  // 108544 B
  const int smem2 = 4 * STG2_H * 2;               // 81920 B
  cudaFuncSetAttribute(tt_gemm1, cudaFuncAttributeMaxDynamicSharedMemorySize, smem1);
  cudaFuncSetAttribute(tt_gemm2, cudaFuncAttributeMaxDynamicSharedMemorySize, smem2);

  prep_h34<<<1024, 256>>>(G3, G4);
  prep_h12<<<1024, 256>>>(G1, G2);
  round_x<<<in_sizes[0] / 1024, 256>>>(x);

  // GEMM1: grid (8 mtiles x 2 ntiles, nb/NGRP sample-groups)
  tt_gemm1<<<dim3(16, nb / NGRP), 256, smem1>>>(pH34, pXr, pM1);
  // GEMM2: grid (2 mtiles x 2 ntiles, nb/NGRP2 sample-groups)
  tt_gemm2<<<dim3(4, nb / NGRP2), 256, smem2>>>(pH12, pM1, out, bias);
}

// round 14
// speedup vs baseline: 1.2230x; 1.0303x over previous
#include <cuda_runtime.h>
#include <cuda_fp16.h>
#include <cstdint>

// TT layer via merged-core fp16 mma.sync GEMMs (m16n8k16, fp32 accumulate).
// Round 14: GEMM1 = r10 proven config (resident A, 8-sample streaming,
// 4-stage k32, wait_group 2). GEMM2 = per-sample, k64 chunks, 3 stages,
// wait_group 1 (half the barriers, prefetch distance still 2 chunks).
// out[n,ab,cd] = relu( sum H12[ab,(s,ij)] x[n,ij,kl] H34[(cd,s),kl] + bias )
// GEMM1 per n: M1[cds, ij] = H34 . Xr[n]^T   M=1024 N=256 K=256
// GEMM2 per n: out[ab, cd] = H12 . M1[n]^T   M=256  N=256 K=1024 (+bias,relu)

__device__ __half g_H34[262144];
__device__ __half g_H12[262144];
__device__ __half g_Xr[67108864];   // RNE-rounded x (128 MB)
__device__ __half g_M1[268435456];  // M1 fp16 (512 MB)

__device__ __forceinline__ uint32_t smem_u32(const void* p) {
  uint32_t a;
  asm("{ .reg .u64 t; cvta.to.shared.u64 t, %1; cvt.u32.u64 %0, t; }" : "=r"(a) : "l"(p));
  return a;
}
__device__ __forceinline__ void cp16(uint32_t s, const __half* g) {
  asm volatile("cp.async.cg.shared.global [%0], [%1], 16;" :: "r"(s), "l"(g));
}
__device__ __forceinline__ void mma_f16(float* c, const uint32_t* a, uint32_t b0, uint32_t b1) {
  asm volatile(
      "mma.sync.aligned.m16n8k16.row.col.f32.f16.f16.f32 "
      "{%0,%1,%2,%3}, {%4,%5,%6,%7}, {%8,%9}, {%0,%1,%2,%3};"
      : "+f"(c[0]), "+f"(c[1]), "+f"(c[2]), "+f"(c[3])
      : "r"(a[0]), "r"(a[1]), "r"(a[2]), "r"(a[3]), "r"(b0), "r"(b1));
}
__device__ __forceinline__ void ldsm_x4(uint32_t* r, uint32_t addr) {
  asm volatile("ldmatrix.sync.aligned.m8n8.x4.shared.b16 {%0,%1,%2,%3}, [%4];"
               : "=r"(r[0]), "=r"(r[1]), "=r"(r[2]), "=r"(r[3]) : "r"(addr));
}

// ---------------- precompute (fp32 math, RNE fp16 store) ----------------
__global__ void prep_h34(const float* __restrict__ G3, const float* __restrict__ G4) {
  int e = blockIdx.x * 256 + threadIdx.x;
  int col = e & 255, row = e >> 8;
  int s = row & 3, cd = row >> 2;
  int c = cd >> 4, d = cd & 15, k = col >> 4, l = col & 15;
  float acc = 0.f;
#pragma unroll
  for (int tt = 0; tt < 4; ++tt)
    acc += G3[((c * 16 + k) * 4 + s) * 4 + tt] * G4[(d * 16 + l) * 4 + tt];
  g_H34[e] = __float2half_rn(acc);
}
__global__ void prep_h12(const float* __restrict__ G1, const float* __restrict__ G2) {
  int e = blockIdx.x * 256 + threadIdx.x;
  int ab = e >> 10, k = e & 1023;
  int s = k >> 8, ij = k & 255;
  int a = ab >> 4, b = ab & 15, i = ij >> 4, j = ij & 15;
  float acc = 0.f;
#pragma unroll
  for (int r = 0; r < 4; ++r)
    acc += G1[(a * 16 + i) * 4 + r] * G2[((b * 16 + j) * 4 + r) * 4 + s];
  g_H12[e] = __float2half_rn(acc);
}
__global__ __launch_bounds__(256) void round_x(const float* __restrict__ x) {
  size_t idx = (size_t)blockIdx.x * 256 + threadIdx.x;
  float4 v = *(const float4*)(x + idx * 4);
  __half2 h0 = __floats2half2_rn(v.x, v.y);
  __half2 h1 = __floats2half2_rn(v.z, v.w);
  uint2 o = { *(uint32_t*)&h0, *(uint32_t*)&h1 };
  *(uint2*)(g_Xr + idx * 4) = o;
}

#define PADH 40
#define PADA 264          // resident A row stride in halves (256 + 8)
#define A_RES_H 33792     // 128 * PADA
#define B_STG_H 5120      // GEMM1 B stage: 128 rows * PADH
#define NGRP 8            // samples per GEMM1 CTA

// ============ GEMM1: M1[n] = H34_mtile . Xr[n]^T, A resident ============
// CTA 128x128; K=256 = 8 chunks of 32; NGRP samples streamed; 4-stage B
// pipeline, wait_group 2. (r10 proven config.)
__global__ __launch_bounds__(256, 2) void tt_gemm1(
    const __half* __restrict__ A, const __half* __restrict__ B,
    __half* __restrict__ C) {
  extern __shared__ __align__(16) __half smh[];
  const int t = threadIdx.x;
  const int lane = t & 31, wid = t >> 5;
  const int grp = lane >> 2, tg = lane & 3;
  const int nt = blockIdx.x & 1, mt = blockIdx.x >> 1;
  const int nbase = blockIdx.y * NGRP;
  const int wm = (wid & 3) * 32, wn = (wid >> 2) * 64;

  const uint32_t base = smem_u32(smh);
  const uint32_t bbase = base + A_RES_H * 2u;

  {
    const __half* Am = A + (long long)mt * 128 * 256;
#pragma unroll
    for (int rep = 0; rep < 16; ++rep) {
      int idx = rep * 256 + t;
      int row = idx >> 5, seg = idx & 31;
      cp16(base + (uint32_t)(row * PADA + seg * 8) * 2u, Am + row * 256 + seg * 8);
    }
    asm volatile("cp.async.commit_group;" ::: "memory");
  }

  uint32_t aOff[2];
#pragma unroll
  for (int mi = 0; mi < 2; ++mi)
    aOff[mi] = (uint32_t)((wm + mi * 16 + (lane & 15)) * PADA + (lane >> 4) * 8) * 2u;
  uint32_t bOff[4];
#pragma unroll
  for (int q = 0; q < 4; ++q)
    bOff[q] = (uint32_t)((wn + q * 16 + (lane & 7) + ((lane >> 4) << 3)) * PADH +
                         (((lane >> 3) & 1) << 3)) * 2u;

  const int srow = t >> 2, sq = t & 3;
  const uint32_t stB = bbase + (uint32_t)(srow * PADH + sq * 8) * 2u;
  const __half* Bnt = B + (long long)nt * 128 * 256;

#pragma unroll
  for (int pch = 0; pch < 3; ++pch) {
    const __half* gb = Bnt + (long long)nbase * 65536 + pch * 32;
    const uint32_t so = (uint32_t)pch * B_STG_H * 2u;
#pragma unroll
    for (int rep = 0; rep < 2; ++rep)
      cp16(stB + so + rep * 64u * PADH * 2u, gb + (long long)(srow + rep * 64) * 256 + sq * 8);
    asm volatile("cp.async.commit_group;" ::: "memory");
  }

  float acc[2][8][4];
#pragma unroll
  for (int mi = 0; mi < 2; ++mi)
#pragma unroll
    for (int ni = 0; ni < 8; ++ni)
#pragma unroll
      for (int q = 0; q < 4; ++q) acc[mi][ni][q] = 0.f;

  for (int gc = 0; gc < 8 * NGRP; ++gc) {
    const int ch = gc & 7;
    asm volatile("cp.async.wait_group 2;" ::: "memory");
    __syncthreads();

    if (gc + 3 < 8 * NGRP) {
      int g2 = gc + 3;
      const __half* gb = Bnt + (long long)(nbase + (g2 >> 3)) * 65536 + (g2 & 7) * 32;
      const uint32_t so = (uint32_t)(g2 & 3) * B_STG_H * 2u;
#pragma unroll
      for (int rep = 0; rep < 2; ++rep)
        cp16(stB + so + rep * 64u * PADH * 2u, gb + (long long)(srow + rep * 64) * 256 + sq * 8);
    }
    asm volatile("cp.async.commit_group;" ::: "memory");

    const uint32_t sa = base + (uint32_t)ch * 64u;
    const uint32_t sb = bbase + (uint32_t)(gc & 3) * B_STG_H * 2u;
#pragma unroll
    for (int sel = 0; sel < 2; ++sel) {
      const uint32_t ko = (uint32_t)sel * 32u;
      uint32_t a[2][4], b[4][4];
      ldsm_x4(a[0], sa + aOff[0] + ko);
      ldsm_x4(a[1], sa + aOff[1] + ko);
#pragma unroll
      for (int q = 0; q < 4; ++q) ldsm_x4(b[q], sb + bOff[q] + ko);
#pragma unroll
      for (int q = 0; q < 4; ++q)
#pragma unroll
        for (int mi = 0; mi < 2; ++mi) {
          mma_f16(acc[mi][2 * q],     a[mi], b[q][0], b[q][1]);
          mma_f16(acc[mi][2 * q + 1], a[mi], b[q][2], b[q][3]);
        }
    }

    if (ch == 7) {
      const int n = nbase + (gc >> 3);
      __half* Cn = C + (long long)n * 262144;
#pragma unroll
      for (int mi = 0; mi < 2; ++mi) {
        int r0 = mt * 128 + wm + mi * 16 + grp;
#pragma unroll
        for (int ni = 0; ni < 8; ++ni) {
          int col = nt * 128 + wn + ni * 8 + 2 * tg;
          __half2 h01 = __floats2half2_rn(acc[mi][ni][0], acc[mi][ni][1]);
          __half2 h23 = __floats2half2_rn(acc[mi][ni][2], acc[mi][ni][3]);
          *(uint32_t*)(Cn + (long long)r0 * 256 + col) = *(uint32_t*)&h01;
          *(uint32_t*)(Cn + (long long)(r0 + 8) * 256 + col) = *(uint32_t*)&h23;
#pragma unroll
          for (int q = 0; q < 4; ++q) acc[mi][ni][q] = 0.f;
        }
      }
    }
  }
}

// ============ GEMM2: out[n] = H12 . M1[n]^T, k64 / 3-stage ============
// CTA 128x128, per-sample. K=1024 = 16 chunks of 64. 3 stages, wait_group 1
// (prefetch distance 2 chunks). PADK=72 halves: ldmatrix conflict-free
// (9 16B-units/row, odd) and 8x16B cp.async segs per row.
#define PADK 72
#define STG64_H 18432   // (128 A rows + 128 B rows) * PADK halves

__global__ __launch_bounds__(256, 2) void tt_gemm2(
    const __half* __restrict__ A, const __half* __restrict__ Bbase,
    float* __restrict__ Cbase, const float* __restrict__ bias) {
  extern __shared__ __align__(16) __half smh[];
  const int t = threadIdx.x;
  const int lane = t & 31, wid = t >> 5;
  const int grp = lane >> 2, tg = lane & 3;
  const int nt = blockIdx.x & 1, mt = blockIdx.x >> 1;
  const int n = blockIdx.y;
  const int wm = (wid & 3) * 32, wn = (wid >> 2) * 64;
  const int K = 1024;

  const __half* Am = A + (long long)mt * 128 * K;
  const __half* Bn = Bbase + (long long)n * 262144 + (long long)nt * 128 * K;

  // loader: 64 halves/row = 8 segs of 16B; srow = t>>3 (0..31, +32/rep), sq = t&7
  const int srow = t >> 3, sq = t & 7;
  const uint32_t base = smem_u32(smh);
  const uint32_t stA = base + (uint32_t)(srow * PADK + sq * 8) * 2u;
  const uint32_t stB = stA + (uint32_t)128 * PADK * 2u;

  uint32_t aOff[2];
#pragma unroll
  for (int mi = 0; mi < 2; ++mi)
    aOff[mi] = (uint32_t)((wm + mi * 16 + (lane & 15)) * PADK + (lane >> 4) * 8) * 2u;
  uint32_t bOff[4];
#pragma unroll
  for (int q = 0; q < 4; ++q)
    bOff[q] = (uint32_t)((wn + q * 16 + (lane & 7) + ((lane >> 4) << 3)) * PADK +
                         (((lane >> 3) & 1) << 3)) * 2u + (uint32_t)128 * PADK * 2u;

  float acc[2][8][4];
#pragma unroll
  for (int mi = 0; mi < 2; ++mi)
#pragma unroll
    for (int ni = 0; ni < 8; ++ni)
#pragma unroll
      for (int q = 0; q < 4; ++q) acc[mi][ni][q] = 0.f;

  const int nch = 16;  // K/64

  // prologue: chunks 0,1 -> stages 0,1
#pragma unroll
  for (int pch = 0; pch < 2; ++pch) {
    const __half* ga = Am + pch * 64;
    const __half* gb = Bn + pch * 64;
    const uint32_t so = (uint32_t)pch * STG64_H * 2u;
#pragma unroll
    for (int rep = 0; rep < 4; ++rep) {
      cp16(stA + so + rep * 32u * PADK * 2u, ga + (long long)(srow + rep * 32) * K + sq * 8);
      cp16(stB + so + rep * 32u * PADK * 2u, gb + (long long)(srow + rep * 32) * K + sq * 8);
    }
    asm volatile("cp.async.commit_group;" ::: "memory");
  }

  for (int ch = 0; ch < nch; ++ch) {
    asm volatile("cp.async.wait_group 1;" ::: "memory");
    __syncthreads();

    // prefetch chunk ch+2 into stage (ch+2)%3 (freed: all warps finished
    // chunk ch-1 at the sync above)
    if (ch + 2 < nch) {
      const __half* ga = Am + (ch + 2) * 64;
      const __half* gb = Bn + (ch + 2) * 64;
      const uint32_t so = (uint32_t)((ch + 2) % 3) * STG64_H * 2u;
#pragma unroll
      for (int rep = 0; rep < 4; ++rep) {
        cp16(stA + so + rep * 32u * PADK * 2u, ga + (long long)(srow + rep * 32) * K + sq * 8);
        cp16(stB + so + rep * 32u * PADK * 2u, gb + (long long)(srow + rep * 32) * K + sq * 8);
      }
    }
    asm volatile("cp.async.commit_group;" ::: "memory");

    const uint32_t sbase = base + (uint32_t)(ch % 3) * STG64_H * 2u;
#pragma unroll
    for (int sel = 0; sel < 4; ++sel) {  // four k16 steps per 64-chunk
      const uint32_t ko = (uint32_t)sel * 32u;  // 16 halves
      uint32_t a[2][4], b[4][4];
      ldsm_x4(a[0], sbase + aOff[0] + ko);
      ldsm_x4(a[1], sbase + aOff[1] + ko);
#pragma unroll
      for (int q = 0; q < 4; ++q) ldsm_x4(b[q], sbase + bOff[q] + ko);
#pragma unroll
      for (int q = 0; q < 4; ++q)
#pragma unroll
        for (int mi = 0; mi < 2; ++mi) {
          mma_f16(acc[mi][2 * q],     a[mi], b[q][0], b[q][1]);
          mma_f16(acc[mi][2 * q + 1], a[mi], b[q][2], b[q][3]);
        }
    }
  }

  float* Cn = Cbase + (long long)n * 65536;
#pragma unroll
  for (int mi = 0; mi < 2; ++mi) {
    int r0 = mt * 128 + wm + mi * 16 + grp;
#pragma unroll
    for (int ni = 0; ni < 8; ++ni) {
      int col = nt * 128 + wn + ni * 8 + 2 * tg;
      float v0 = fmaxf(acc[mi][ni][0] + bias[r0 * 256 + col], 0.f);
      float v1 = fmaxf(acc[mi][ni][1] + bias[r0 * 256 + col + 1], 0.f);
      float v2 = fmaxf(acc[mi][ni][2] + bias[(r0 + 8) * 256 + col], 0.f);
      float v3 = fmaxf(acc[mi][ni][3] + bias[(r0 + 8) * 256 + col + 1], 0.f);
      *(float2*)(Cn + (long long)r0 * 256 + col) = make_float2(v0, v1);
      *(float2*)(Cn + (long long)(r0 + 8) * 256 + col) = make_float2(v2, v3);
    }
  }
}

// ---------------- launch ----------------
extern "C" void kernel_launch(void* const* d_in, const int* in_sizes, int n_in,
                              void* d_out, int out_size) {
  const float* x    = (const float*)d_in[0];
  const float* G1   = (const float*)d_in[1];
  const float* G2   = (const float*)d_in[2];
  const float* G3   = (const float*)d_in[3];
  const float* G4   = (const float*)d_in[4];
  const float* bias = (const float*)d_in[5];
  float* out = (float*)d_out;
  const int nb = in_sizes[0] / 65536;

  __half *pH34, *pH12, *pM1, *pXr;
  cudaGetSymbolAddress((void**)&pH34, g_H34);
  cudaGetSymbolAddress((void**)&pH12, g_H12);
  cudaGetSymbolAddress((void**)&pM1, g_M1);
  cudaGetSymbolAddress((void**)&pXr, g_Xr);

  const int smem1 = (A_RES_H + 4 * B_STG_H) * 2;  // 108544 B
  const int smem2 = 3 * STG64_H * 2;              // 110592 B
  cudaFuncSetAttribute(tt_gemm1, cudaFuncAttributeMaxDynamicSharedMemorySize, smem1);
  cudaFuncSetAttribute(tt_gemm2, cudaFuncAttributeMaxDynamicSharedMemorySize, smem2);

  prep_h34<<<1024, 256>>>(G3, G4);
  prep_h12<<<1024, 256>>>(G1, G2);
  round_x<<<in_sizes[0] / 1024, 256>>>(x);

  // GEMM1: grid (8 mtiles x 2 ntiles, nb/NGRP sample-groups)
  tt_gemm1<<<dim3(16, nb / NGRP), 256, smem1>>>(pH34, pXr, pM1);
  // GEMM2: grid (2 mtiles x 2 ntiles, nb samples)
  tt_gemm2<<<dim3(4, nb), 256, smem2>>>(pH12, pM1, out, bias);
}

// round 15
// speedup vs baseline: 1.2394x; 1.0134x over previous
#include <cuda_runtime.h>
#include <cuda_fp16.h>
#include <cstdint>

// TT layer via merged-core fp16 mma.sync GEMMs (m16n8k16, fp32 accumulate).
// Round 15: GEMM1 splits its CTA into two independent 4-warp barrier domains
// (named bar.sync, per-half B loading; A resident & read-only) — no extra
// L2 traffic, half the barrier scope. GEMM2 = r14 (k64 / 3-stage / wg1).
// out[n,ab,cd] = relu( sum H12[ab,(s,ij)] x[n,ij,kl] H34[(cd,s),kl] + bias )
// GEMM1 per n: M1[cds, ij] = H34 . Xr[n]^T   M=1024 N=256 K=256
// GEMM2 per n: out[ab, cd] = H12 . M1[n]^T   M=256  N=256 K=1024 (+bias,relu)

__device__ __half g_H34[262144];
__device__ __half g_H12[262144];
__device__ __half g_Xr[67108864];   // RNE-rounded x (128 MB)
__device__ __half g_M1[268435456];  // M1 fp16 (512 MB)

__device__ __forceinline__ uint32_t smem_u32(const void* p) {
  uint32_t a;
  asm("{ .reg .u64 t; cvta.to.shared.u64 t, %1; cvt.u32.u64 %0, t; }" : "=r"(a) : "l"(p));
  return a;
}
__device__ __forceinline__ void cp16(uint32_t s, const __half* g) {
  asm volatile("cp.async.cg.shared.global [%0], [%1], 16;" :: "r"(s), "l"(g));
}
__device__ __forceinline__ void mma_f16(float* c, const uint32_t* a, uint32_t b0, uint32_t b1) {
  asm volatile(
      "mma.sync.aligned.m16n8k16.row.col.f32.f16.f16.f32 "
      "{%0,%1,%2,%3}, {%4,%5,%6,%7}, {%8,%9}, {%0,%1,%2,%3};"
      : "+f"(c[0]), "+f"(c[1]), "+f"(c[2]), "+f"(c[3])
      : "r"(a[0]), "r"(a[1]), "r"(a[2]), "r"(a[3]), "r"(b0), "r"(b1));
}
__device__ __forceinline__ void ldsm_x4(uint32_t* r, uint32_t addr) {
  asm volatile("ldmatrix.sync.aligned.m8n8.x4.shared.b16 {%0,%1,%2,%3}, [%4];"
               : "=r"(r[0]), "=r"(r[1]), "=r"(r[2]), "=r"(r[3]) : "r"(addr));
}
__device__ __forceinline__ void bar_half(int id) {
  asm volatile("bar.sync %0, 128;" :: "r"(id) : "memory");
}

// ---------------- precompute (fp32 math, RNE fp16 store) ----------------
__global__ void prep_h34(const float* __restrict__ G3, const float* __restrict__ G4) {
  int e = blockIdx.x * 256 + threadIdx.x;
  int col = e & 255, row = e >> 8;
  int s = row & 3, cd = row >> 2;
  int c = cd >> 4, d = cd & 15, k = col >> 4, l = col & 15;
  float acc = 0.f;
#pragma unroll
  for (int tt = 0; tt < 4; ++tt)
    acc += G3[((c * 16 + k) * 4 + s) * 4 + tt] * G4[(d * 16 + l) * 4 + tt];
  g_H34[e] = __float2half_rn(acc);
}
__global__ void prep_h12(const float* __restrict__ G1, const float* __restrict__ G2) {
  int e = blockIdx.x * 256 + threadIdx.x;
  int ab = e >> 10, k = e & 1023;
  int s = k >> 8, ij = k & 255;
  int a = ab >> 4, b = ab & 15, i = ij >> 4, j = ij & 15;
  float acc = 0.f;
#pragma unroll
  for (int r = 0; r < 4; ++r)
    acc += G1[(a * 16 + i) * 4 + r] * G2[((b * 16 + j) * 4 + r) * 4 + s];
  g_H12[e] = __float2half_rn(acc);
}
__global__ __launch_bounds__(256) void round_x(const float* __restrict__ x) {
  size_t idx = (size_t)blockIdx.x * 256 + threadIdx.x;
  float4 v = *(const float4*)(x + idx * 4);
  __half2 h0 = __floats2half2_rn(v.x, v.y);
  __half2 h1 = __floats2half2_rn(v.z, v.w);
  uint2 o = { *(uint32_t*)&h0, *(uint32_t*)&h1 };
  *(uint2*)(g_Xr + idx * 4) = o;
}

#define PADH 40
#define PADA 264          // resident A row stride in halves (256 + 8)
#define A_RES_H 33792     // 128 * PADA
#define B_STG_H 5120      // GEMM1 B stage: 128 rows * PADH
#define NGRP 8            // samples per GEMM1 CTA

// ============ GEMM1: M1[n] = H34_mtile . Xr[n]^T, A resident ============
// CTA 128x128; K=256 = 8 chunks of 32; NGRP samples streamed; 4-stage B
// pipeline, wait_group 2. Two independent 4-warp halves: half h = wid>>2
// consumes/loads only B rows [h*64, h*64+64); named bar.sync per half.
__global__ __launch_bounds__(256, 2) void tt_gemm1(
    const __half* __restrict__ A, const __half* __restrict__ B,
    __half* __restrict__ C) {
  extern __shared__ __align__(16) __half smh[];
  const int t = threadIdx.x;
  const int lane = t & 31, wid = t >> 5;
  const int grp = lane >> 2, tg = lane & 3;
  const int nt = blockIdx.x & 1, mt = blockIdx.x >> 1;
  const int nbase = blockIdx.y * NGRP;
  const int wm = (wid & 3) * 32, wn = (wid >> 2) * 64;
  const int h = wid >> 2;            // half id (0/1)

  const uint32_t base = smem_u32(smh);
  const uint32_t bbase = base + A_RES_H * 2u;

  // resident A tile: 128 rows x 256 halves (all threads)
  {
    const __half* Am = A + (long long)mt * 128 * 256;
#pragma unroll
    for (int rep = 0; rep < 16; ++rep) {
      int idx = rep * 256 + t;
      int row = idx >> 5, seg = idx & 31;
      cp16(base + (uint32_t)(row * PADA + seg * 8) * 2u, Am + row * 256 + seg * 8);
    }
    asm volatile("cp.async.commit_group;" ::: "memory");
  }

  uint32_t aOff[2];
#pragma unroll
  for (int mi = 0; mi < 2; ++mi)
    aOff[mi] = (uint32_t)((wm + mi * 16 + (lane & 15)) * PADA + (lane >> 4) * 8) * 2u;
  uint32_t bOff[4];
#pragma unroll
  for (int q = 0; q < 4; ++q)
    bOff[q] = (uint32_t)((wn + q * 16 + (lane & 7) + ((lane >> 4) << 3)) * PADH +
                         (((lane >> 3) & 1) << 3)) * 2u;

  // per-half B loader: 64 rows x 32 halves per chunk = 256 segs / 128 thr
  // local tid l = t&127; per rep: row = h*64 + rep*32 + (l>>2), seg = l&3.
  const int l = t & 127;
  const int lrow = l >> 2, lsq = l & 3;
  const uint32_t stB = bbase +
      (uint32_t)((h * 64 + lrow) * PADH + lsq * 8) * 2u;
  const __half* Bnt = B + (long long)nt * 128 * 256;
  const int grow = h * 64 + lrow;  // global B row base for this thread

  // prologue: B chunks 0,1,2 of sample nbase (own half's rows)
#pragma unroll
  for (int pch = 0; pch < 3; ++pch) {
    const __half* gb = Bnt + (long long)nbase * 65536 + pch * 32;
    const uint32_t so = (uint32_t)pch * B_STG_H * 2u;
#pragma unroll
    for (int rep = 0; rep < 2; ++rep)
      cp16(stB + so + rep * 32u * PADH * 2u,
           gb + (long long)(grow + rep * 32) * 256 + lsq * 8);
    asm volatile("cp.async.commit_group;" ::: "memory");
  }

  float acc[2][8][4];
#pragma unroll
  for (int mi = 0; mi < 2; ++mi)
#pragma unroll
    for (int ni = 0; ni < 8; ++ni)
#pragma unroll
      for (int q = 0; q < 4; ++q) acc[mi][ni][q] = 0.f;

  for (int gc = 0; gc < 8 * NGRP; ++gc) {
    const int ch = gc & 7;
    asm volatile("cp.async.wait_group 2;" ::: "memory");
    if (gc == 0) __syncthreads();    // full: A visibility across halves
    else bar_half(1 + h);            // own half only

    if (gc + 3 < 8 * NGRP) {
      int g2 = gc + 3;
      const __half* gb = Bnt + (long long)(nbase + (g2 >> 3)) * 65536 + (g2 & 7) * 32;
      const uint32_t so = (uint32_t)(g2 & 3) * B_STG_H * 2u;
#pragma unroll
      for (int rep = 0; rep < 2; ++rep)
        cp16(stB + so + rep * 32u * PADH * 2u,
             gb + (long long)(grow + rep * 32) * 256 + lsq * 8);
    }
    asm volatile("cp.async.commit_group;" ::: "memory");

    const uint32_t sa = base + (uint32_t)ch * 64u;
    const uint32_t sb = bbase + (uint32_t)(gc & 3) * B_STG_H * 2u;
#pragma unroll
    for (int sel = 0; sel < 2; ++sel) {
      const uint32_t ko = (uint32_t)sel * 32u;
      uint32_t a[2][4], b[4][4];
      ldsm_x4(a[0], sa + aOff[0] + ko);
      ldsm_x4(a[1], sa + aOff[1] + ko);
#pragma unroll
      for (int q = 0; q < 4; ++q) ldsm_x4(b[q], sb + bOff[q] + ko);
#pragma unroll
      for (int q = 0; q < 4; ++q)
#pragma unroll
        for (int mi = 0; mi < 2; ++mi) {
          mma_f16(acc[mi][2 * q],     a[mi], b[q][0], b[q][1]);
          mma_f16(acc[mi][2 * q + 1], a[mi], b[q][2], b[q][3]);
        }
    }

    if (ch == 7) {  // sample epilogue (no cross-warp dependency)
      const int n = nbase + (gc >> 3);
      __half* Cn = C + (long long)n * 262144;
#pragma unroll
      for (int mi = 0; mi < 2; ++mi) {
        int r0 = mt * 128 + wm + mi * 16 + grp;
#pragma unroll
        for (int ni = 0; ni < 8; ++ni) {
          int col = nt * 128 + wn + ni * 8 + 2 * tg;
          __half2 h01 = __floats2half2_rn(acc[mi][ni][0], acc[mi][ni][1]);
          __half2 h23 = __floats2half2_rn(acc[mi][ni][2], acc[mi][ni][3]);
          *(uint32_t*)(Cn + (long long)r0 * 256 + col) = *(uint32_t*)&h01;
          *(uint32_t*)(Cn + (long long)(r0 + 8) * 256 + col) = *(uint32_t*)&h23;
#pragma unroll
          for (int q = 0; q < 4; ++q) acc[mi][ni][q] = 0.f;
        }
      }
    }
  }
}

// ============ GEMM2: out[n] = H12 . M1[n]^T, k64 / 3-stage (r14) ============
#define PADK 72
#define STG64_H 18432   // (128 A rows + 128 B rows) * PADK halves

__global__ __launch_bounds__(256, 2) void tt_gemm2(
    const __half* __restrict__ A, const __half* __restrict__ Bbase,
    float* __restrict__ Cbase, const float* __restrict__ bias) {
  extern __shared__ __align__(16) __half smh[];
  const int t = threadIdx.x;
  const int lane = t & 31, wid = t >> 5;
  const int grp = lane >> 2, tg = lane & 3;
  const int nt = blockIdx.x & 1, mt = blockIdx.x >> 1;
  const int n = blockIdx.y;
  const int wm = (wid & 3) * 32, wn = (wid >> 2) * 64;
  const int K = 1024;

  const __half* Am = A + (long long)mt * 128 * K;
  const __half* Bn = Bbase + (long long)n * 262144 + (long long)nt * 128 * K;

  const int srow = t >> 3, sq = t & 7;
  const uint32_t base = smem_u32(smh);
  const uint32_t stA = base + (uint32_t)(srow * PADK + sq * 8) * 2u;
  const uint32_t stB = stA + (uint32_t)128 * PADK * 2u;

  uint32_t aOff[2];
#pragma unroll
  for (int mi = 0; mi < 2; ++mi)
    aOff[mi] = (uint32_t)((wm + mi * 16 + (lane & 15)) * PADK + (lane >> 4) * 8) * 2u;
  uint32_t bOff[4];
#pragma unroll
  for (int q = 0; q < 4; ++q)
    bOff[q] = (uint32_t)((wn + q * 16 + (lane & 7) + ((lane >> 4) << 3)) * PADK +
                         (((lane >> 3) & 1) << 3)) * 2u + (uint32_t)128 * PADK * 2u;

  float acc[2][8][4];
#pragma unroll
  for (int mi = 0; mi < 2; ++mi)
#pragma unroll
    for (int ni = 0; ni < 8; ++ni)
#pragma unroll
      for (int q = 0; q < 4; ++q) acc[mi][ni][q] = 0.f;

  const int nch = 16;  // K/64

#pragma unroll
  for (int pch = 0; pch < 2; ++pch) {
    const __half* ga = Am + pch * 64;
    const __half* gb = Bn + pch * 64;
    const uint32_t so = (uint32_t)pch * STG64_H * 2u;
#pragma unroll
    for (int rep = 0; rep < 4; ++rep) {
      cp16(stA + so + rep * 32u * PADK * 2u, ga + (long long)(srow + rep * 32) * K + sq * 8);
      cp16(stB + so + rep * 32u * PADK * 2u, gb + (long long)(srow + rep * 32) * K + sq * 8);
    }
    asm volatile("cp.async.commit_group;" ::: "memory");
  }

  for (int ch = 0; ch < nch; ++ch) {
    asm volatile("cp.async.wait_group 1;" ::: "memory");
    __syncthreads();

    if (ch + 2 < nch) {
      const __half* ga = Am + (ch + 2) * 64;
      const __half* gb = Bn + (ch + 2) * 64;
      const uint32_t so = (uint32_t)((ch + 2) % 3) * STG64_H * 2u;
#pragma unroll
      for (int rep = 0; rep < 4; ++rep) {
        cp16(stA + so + rep * 32u * PADK * 2u, ga + (long long)(srow + rep * 32) * K + sq * 8);
        cp16(stB + so + rep * 32u * PADK * 2u, gb + (long long)(srow + rep * 32) * K + sq * 8);
      }
    }
    asm volatile("cp.async.commit_group;" ::: "memory");

    const uint32_t sbase = base + (uint32_t)(ch % 3) * STG64_H * 2u;
#pragma unroll
    for (int sel = 0; sel < 4; ++sel) {
      const uint32_t ko = (uint32_t)sel * 32u;
      uint32_t a[2][4], b[4][4];
      ldsm_x4(a[0], sbase + aOff[0] + ko);
      ldsm_x4(a[1], sbase + aOff[1] + ko);
#pragma unroll
      for (int q = 0; q < 4; ++q) ldsm_x4(b[q], sbase + bOff[q] + ko);
#pragma unroll
      for (int q = 0; q < 4; ++q)
#pragma unroll
        for (int mi = 0; mi < 2; ++mi) {
          mma_f16(acc[mi][2 * q],     a[mi], b[q][0], b[q][1]);
          mma_f16(acc[mi][2 * q + 1], a[mi], b[q][2], b[q][3]);
        }
    }
  }

  float* Cn = Cbase + (long long)n * 65536;
#pragma unroll
  for (int mi = 0; mi < 2; ++mi) {
    int r0 = mt * 128 + wm + mi * 16 + grp;
#pragma unroll
    for (int ni = 0; ni < 8; ++ni) {
      int col = nt * 128 + wn + ni * 8 + 2 * tg;
      float v0 = fmaxf(acc[mi][ni][0] + bias[r0 * 256 + col], 0.f);
      float v1 = fmaxf(acc[mi][ni][1] + bias[r0 * 256 + col + 1], 0.f);
      float v2 = fmaxf(acc[mi][ni][2] + bias[(r0 + 8) * 256 + col], 0.f);
      float v3 = fmaxf(acc[mi][ni][3] + bias[(r0 + 8) * 256 + col + 1], 0.f);
      *(float2*)(Cn + (long long)r0 * 256 + col) = make_float2(v0, v1);
      *(float2*)(Cn + (long long)(r0 + 8) * 256 + col) = make_float2(v2, v3);
    }
  }
}

// ---------------- launch ----------------
extern "C" void kernel_launch(void* const* d_in, const int* in_sizes, int n_in,
                              void* d_out, int out_size) {
  const float* x    = (const float*)d_in[0];
  const float* G1   = (const float*)d_in[1];
  const float* G2   = (const float*)d_in[2];
  const float* G3   = (const float*)d_in[3];
  const float* G4   = (const float*)d_in[4];
  const float* bias = (const float*)d_in[5];
  float* out = (float*)d_out;
  const int nb = in_sizes[0] / 65536;

  __half *pH34, *pH12, *pM1, *pXr;
  cudaGetSymbolAddress((void**)&pH34, g_H34);
  cudaGetSymbolAddress((void**)&pH12, g_H12);
  cudaGetSymbolAddress((void**)&pM1, g_M1);
  cudaGetSymbolAddress((void**)&pXr, g_Xr);

  const int smem1 = (A_RES_H + 4 * B_STG_H) * 2;  // 108544 B
  const int smem2 = 3 * STG64_H * 2;              // 110592 B
  cudaFuncSetAttribute(tt_gemm1, cudaFuncAttributeMaxDynamicSharedMemorySize, smem1);
  cudaFuncSetAttribute(tt_gemm2, cudaFuncAttributeMaxDynamicSharedMemorySize, smem2);

  prep_h34<<<1024, 256>>>(G3, G4);
  prep_h12<<<1024, 256>>>(G1, G2);
  round_x<<<in_sizes[0] / 1024, 256>>>(x);

  // GEMM1: grid (8 mtiles x 2 ntiles, nb/NGRP sample-groups)
  tt_gemm1<<<dim3(16, nb / NGRP), 256, smem1>>>(pH34, pXr, pM1);
  // GEMM2: grid (2 mtiles x 2 ntiles, nb samples)
  tt_gemm2<<<dim3(4, nb), 256, smem2>>>(pH12, pM1, out, bias);
}

// round 16
// speedup vs baseline: 1.2855x; 1.0372x over previous
#include <cuda_runtime.h>
#include <cuda_fp16.h>
#include <cstdint>

// TT layer via merged-core fp16 mma.sync GEMMs (m16n8k16, fp32 accumulate).
// Round 16: LDSM-before-prefetch issue order in both GEMM hot loops;
// GEMM1 NGRP=16; prep kernels merged into one launch.
// GEMM1: resident A, split-half barrier domains, 4-stage k32, wg2.
// GEMM2: k64 / 3-stage / wg1 (r14).
// out[n,ab,cd] = relu( sum H12[ab,(s,ij)] x[n,ij,kl] H34[(cd,s),kl] + bias )
// GEMM1 per n: M1[cds, ij] = H34 . Xr[n]^T   M=1024 N=256 K=256
// GEMM2 per n: out[ab, cd] = H12 . M1[n]^T   M=256  N=256 K=1024 (+bias,relu)

__device__ __half g_H34[262144];
__device__ __half g_H12[262144];
__device__ __half g_Xr[67108864];   // RNE-rounded x (128 MB)
__device__ __half g_M1[268435456];  // M1 fp16 (512 MB)

__device__ __forceinline__ uint32_t smem_u32(const void* p) {
  uint32_t a;
  asm("{ .reg .u64 t; cvta.to.shared.u64 t, %1; cvt.u32.u64 %0, t; }" : "=r"(a) : "l"(p));
  return a;
}
__device__ __forceinline__ void cp16(uint32_t s, const __half* g) {
  asm volatile("cp.async.cg.shared.global [%0], [%1], 16;" :: "r"(s), "l"(g));
}
__device__ __forceinline__ void mma_f16(float* c, const uint32_t* a, uint32_t b0, uint32_t b1) {
  asm volatile(
      "mma.sync.aligned.m16n8k16.row.col.f32.f16.f16.f32 "
      "{%0,%1,%2,%3}, {%4,%5,%6,%7}, {%8,%9}, {%0,%1,%2,%3};"
      : "+f"(c[0]), "+f"(c[1]), "+f"(c[2]), "+f"(c[3])
      : "r"(a[0]), "r"(a[1]), "r"(a[2]), "r"(a[3]), "r"(b0), "r"(b1));
}
__device__ __forceinline__ void ldsm_x4(uint32_t* r, uint32_t addr) {
  asm volatile("ldmatrix.sync.aligned.m8n8.x4.shared.b16 {%0,%1,%2,%3}, [%4];"
               : "=r"(r[0]), "=r"(r[1]), "=r"(r[2]), "=r"(r[3]) : "r"(addr));
}
__device__ __forceinline__ void bar_half(int id) {
  asm volatile("bar.sync %0, 128;" :: "r"(id) : "memory");
}

// ---------------- merged precompute: H34 | H12 | round_x ----------------
__global__ __launch_bounds__(256) void prep_all(
    const float* __restrict__ G1, const float* __restrict__ G2,
    const float* __restrict__ G3, const float* __restrict__ G4,
    const float* __restrict__ x) {
  const int bid = blockIdx.x;
  if (bid < 1024) {
    int e = bid * 256 + threadIdx.x;
    int col = e & 255, row = e >> 8;
    int s = row & 3, cd = row >> 2;
    int c = cd >> 4, d = cd & 15, k = col >> 4, l = col & 15;
    float acc = 0.f;
#pragma unroll
    for (int tt = 0; tt < 4; ++tt)
      acc += G3[((c * 16 + k) * 4 + s) * 4 + tt] * G4[(d * 16 + l) * 4 + tt];
    g_H34[e] = __float2half_rn(acc);
  } else if (bid < 2048) {
    int e = (bid - 1024) * 256 + threadIdx.x;
    int ab = e >> 10, k = e & 1023;
    int s = k >> 8, ij = k & 255;
    int a = ab >> 4, b = ab & 15, i = ij >> 4, j = ij & 15;
    float acc = 0.f;
#pragma unroll
    for (int r = 0; r < 4; ++r)
      acc += G1[(a * 16 + i) * 4 + r] * G2[((b * 16 + j) * 4 + r) * 4 + s];
    g_H12[e] = __float2half_rn(acc);
  } else {
    size_t idx = (size_t)(bid - 2048) * 256 + threadIdx.x;
    float4 v = *(const float4*)(x + idx * 4);
    __half2 h0 = __floats2half2_rn(v.x, v.y);
    __half2 h1 = __floats2half2_rn(v.z, v.w);
    uint2 o = { *(uint32_t*)&h0, *(uint32_t*)&h1 };
    *(uint2*)(g_Xr + idx * 4) = o;
  }
}

#define PADH 40
#define PADA 264          // resident A row stride in halves (256 + 8)
#define A_RES_H 33792     // 128 * PADA
#define B_STG_H 5120      // GEMM1 B stage: 128 rows * PADH
#define NGRP 16           // samples per GEMM1 CTA

// ============ GEMM1: M1[n] = H34_mtile . Xr[n]^T, A resident ============
// CTA 128x128; K=256 = 8 chunks of 32; NGRP samples streamed; 4-stage B
// pipeline, wait_group 2. Two independent 4-warp halves (named bar.sync).
__global__ __launch_bounds__(256, 2) void tt_gemm1(
    const __half* __restrict__ A, const __half* __restrict__ B,
    __half* __restrict__ C) {
  extern __shared__ __align__(16) __half smh[];
  const int t = threadIdx.x;
  const int lane = t & 31, wid = t >> 5;
  const int grp = lane >> 2, tg = lane & 3;
  const int nt = blockIdx.x & 1, mt = blockIdx.x >> 1;
  const int nbase = blockIdx.y * NGRP;
  const int wm = (wid & 3) * 32, wn = (wid >> 2) * 64;
  const int h = wid >> 2;            // half id (0/1)

  const uint32_t base = smem_u32(smh);
  const uint32_t bbase = base + A_RES_H * 2u;

  // resident A tile: 128 rows x 256 halves (all threads)
  {
    const __half* Am = A + (long long)mt * 128 * 256;
#pragma unroll
    for (int rep = 0; rep < 16; ++rep) {
      int idx = rep * 256 + t;
      int row = idx >> 5, seg = idx & 31;
      cp16(base + (uint32_t)(row * PADA + seg * 8) * 2u, Am + row * 256 + seg * 8);
    }
    asm volatile("cp.async.commit_group;" ::: "memory");
  }

  uint32_t aOff[2];
#pragma unroll
  for (int mi = 0; mi < 2; ++mi)
    aOff[mi] = (uint32_t)((wm + mi * 16 + (lane & 15)) * PADA + (lane >> 4) * 8) * 2u;
  uint32_t bOff[4];
#pragma unroll
  for (int q = 0; q < 4; ++q)
    bOff[q] = (uint32_t)((wn + q * 16 + (lane & 7) + ((lane >> 4) << 3)) * PADH +
                         (((lane >> 3) & 1) << 3)) * 2u;

  // per-half B loader: 64 rows x 32 halves per chunk
  const int l = t & 127;
  const int lrow = l >> 2, lsq = l & 3;
  const uint32_t stB = bbase + (uint32_t)((h * 64 + lrow) * PADH + lsq * 8) * 2u;
  const __half* Bnt = B + (long long)nt * 128 * 256;
  const int grow = h * 64 + lrow;

  // prologue: B chunks 0,1,2 of sample nbase (own half's rows)
#pragma unroll
  for (int pch = 0; pch < 3; ++pch) {
    const __half* gb = Bnt + (long long)nbase * 65536 + pch * 32;
    const uint32_t so = (uint32_t)pch * B_STG_H * 2u;
#pragma unroll
    for (int rep = 0; rep < 2; ++rep)
      cp16(stB + so + rep * 32u * PADH * 2u,
           gb + (long long)(grow + rep * 32) * 256 + lsq * 8);
    asm volatile("cp.async.commit_group;" ::: "memory");
  }

  float acc[2][8][4];
#pragma unroll
  for (int mi = 0; mi < 2; ++mi)
#pragma unroll
    for (int ni = 0; ni < 8; ++ni)
#pragma unroll
      for (int q = 0; q < 4; ++q) acc[mi][ni][q] = 0.f;

  for (int gc = 0; gc < 8 * NGRP; ++gc) {
    const int ch = gc & 7;
    asm volatile("cp.async.wait_group 2;" ::: "memory");
    if (gc == 0) __syncthreads();
    else bar_half(1 + h);

    const uint32_t sa = base + (uint32_t)ch * 64u;
    const uint32_t sb = bbase + (uint32_t)(gc & 3) * B_STG_H * 2u;

    // sel-0 fragment loads FIRST (critical path), then prefetch, then MMAs
    uint32_t a0[2][4], b0[4][4];
    ldsm_x4(a0[0], sa + aOff[0]);
    ldsm_x4(a0[1], sa + aOff[1]);
#pragma unroll
    for (int q = 0; q < 4; ++q) ldsm_x4(b0[q], sb + bOff[q]);

    if (gc + 3 < 8 * NGRP) {
      int g2 = gc + 3;
      const __half* gb = Bnt + (long long)(nbase + (g2 >> 3)) * 65536 + (g2 & 7) * 32;
      const uint32_t so = (uint32_t)(g2 & 3) * B_STG_H * 2u;
#pragma unroll
      for (int rep = 0; rep < 2; ++rep)
        cp16(stB + so + rep * 32u * PADH * 2u,
             gb + (long long)(grow + rep * 32) * 256 + lsq * 8);
    }
    asm volatile("cp.async.commit_group;" ::: "memory");

#pragma unroll
    for (int q = 0; q < 4; ++q)
#pragma unroll
      for (int mi = 0; mi < 2; ++mi) {
        mma_f16(acc[mi][2 * q],     a0[mi], b0[q][0], b0[q][1]);
        mma_f16(acc[mi][2 * q + 1], a0[mi], b0[q][2], b0[q][3]);
      }

    {  // sel 1
      uint32_t a1[2][4], b1[4][4];
      ldsm_x4(a1[0], sa + aOff[0] + 32u);
      ldsm_x4(a1[1], sa + aOff[1] + 32u);
#pragma unroll
      for (int q = 0; q < 4; ++q) ldsm_x4(b1[q], sb + bOff[q] + 32u);
#pragma unroll
      for (int q = 0; q < 4; ++q)
#pragma unroll
        for (int mi = 0; mi < 2; ++mi) {
          mma_f16(acc[mi][2 * q],     a1[mi], b1[q][0], b1[q][1]);
          mma_f16(acc[mi][2 * q + 1], a1[mi], b1[q][2], b1[q][3]);
        }
    }

    if (ch == 7) {  // sample epilogue
      const int n = nbase + (gc >> 3);
      __half* Cn = C + (long long)n * 262144;
#pragma unroll
      for (int mi = 0; mi < 2; ++mi) {
        int r0 = mt * 128 + wm + mi * 16 + grp;
#pragma unroll
        for (int ni = 0; ni < 8; ++ni) {
          int col = nt * 128 + wn + ni * 8 + 2 * tg;
          __half2 h01 = __floats2half2_rn(acc[mi][ni][0], acc[mi][ni][1]);
          __half2 h23 = __floats2half2_rn(acc[mi][ni][2], acc[mi][ni][3]);
          *(uint32_t*)(Cn + (long long)r0 * 256 + col) = *(uint32_t*)&h01;
          *(uint32_t*)(Cn + (long long)(r0 + 8) * 256 + col) = *(uint32_t*)&h23;
#pragma unroll
          for (int q = 0; q < 4; ++q) acc[mi][ni][q] = 0.f;
        }
      }
    }
  }
}

// ============ GEMM2: out[n] = H12 . M1[n]^T, k64 / 3-stage ============
#define PADK 72
#define STG64_H 18432   // (128 A rows + 128 B rows) * PADK halves

__global__ __launch_bounds__(256, 2) void tt_gemm2(
    const __half* __restrict__ A, const __half* __restrict__ Bbase,
    float* __restrict__ Cbase, const float* __restrict__ bias) {
  extern __shared__ __align__(16) __half smh[];
  const int t = threadIdx.x;
  const int lane = t & 31, wid = t >> 5;
  const int grp = lane >> 2, tg = lane & 3;
  const int nt = blockIdx.x & 1, mt = blockIdx.x >> 1;
  const int n = blockIdx.y;
  const int wm = (wid & 3) * 32, wn = (wid >> 2) * 64;
  const int K = 1024;

  const __half* Am = A + (long long)mt * 128 * K;
  const __half* Bn = Bbase + (long long)n * 262144 + (long long)nt * 128 * K;

  const int srow = t >> 3, sq = t & 7;
  const uint32_t base = smem_u32(smh);
  const uint32_t stA = base + (uint32_t)(srow * PADK + sq * 8) * 2u;
  const uint32_t stB = stA + (uint32_t)128 * PADK * 2u;

  uint32_t aOff[2];
#pragma unroll
  for (int mi = 0; mi < 2; ++mi)
    aOff[mi] = (uint32_t)((wm + mi * 16 + (lane & 15)) * PADK + (lane >> 4) * 8) * 2u;
  uint32_t bOff[4];
#pragma unroll
  for (int q = 0; q < 4; ++q)
    bOff[q] = (uint32_t)((wn + q * 16 + (lane & 7) + ((lane >> 4) << 3)) * PADK +
                         (((lane >> 3) & 1) << 3)) * 2u + (uint32_t)128 * PADK * 2u;

  float acc[2][8][4];
#pragma unroll
  for (int mi = 0; mi < 2; ++mi)
#pragma unroll
    for (int ni = 0; ni < 8; ++ni)
#pragma unroll
      for (int q = 0; q < 4; ++q) acc[mi][ni][q] = 0.f;

  const int nch = 16;  // K/64

#pragma unroll
  for (int pch = 0; pch < 2; ++pch) {
    const __half* ga = Am + pch * 64;
    const __half* gb = Bn + pch * 64;
    const uint32_t so = (uint32_t)pch * STG64_H * 2u;
#pragma unroll
    for (int rep = 0; rep < 4; ++rep) {
      cp16(stA + so + rep * 32u * PADK * 2u, ga + (long long)(srow + rep * 32) * K + sq * 8);
      cp16(stB + so + rep * 32u * PADK * 2u, gb + (long long)(srow + rep * 32) * K + sq * 8);
    }
    asm volatile("cp.async.commit_group;" ::: "memory");
  }

  for (int ch = 0; ch < nch; ++ch) {
    asm volatile("cp.async.wait_group 1;" ::: "memory");
    __syncthreads();

    const uint32_t sbase = base + (uint32_t)(ch % 3) * STG64_H * 2u;

    // sel-0 fragment loads FIRST, then prefetch, then MMAs
    uint32_t a0[2][4], b0[4][4];
    ldsm_x4(a0[0], sbase + aOff[0]);
    ldsm_x4(a0[1], sbase + aOff[1]);
#pragma unroll
    for (int q = 0; q < 4; ++q) ldsm_x4(b0[q], sbase + bOff[q]);

    if (ch + 2 < nch) {
      const __half* ga = Am + (ch + 2) * 64;
      const __half* gb = Bn + (ch + 2) * 64;
      const uint32_t so = (uint32_t)((ch + 2) % 3) * STG64_H * 2u;
#pragma unroll
      for (int rep = 0; rep < 4; ++rep) {
        cp16(stA + so + rep * 32u * PADK * 2u, ga + (long long)(srow + rep * 32) * K + sq * 8);
        cp16(stB + so + rep * 32u * PADK * 2u, gb + (long long)(srow + rep * 32) * K + sq * 8);
      }
    }
    asm volatile("cp.async.commit_group;" ::: "memory");

#pragma unroll
    for (int q = 0; q < 4; ++q)
#pragma unroll
      for (int mi = 0; mi < 2; ++mi) {
        mma_f16(acc[mi][2 * q],     a0[mi], b0[q][0], b0[q][1]);
        mma_f16(acc[mi][2 * q + 1], a0[mi], b0[q][2], b0[q][3]);
      }

#pragma unroll
    for (int sel = 1; sel < 4; ++sel) {
      const uint32_t ko = (uint32_t)sel * 32u;
      uint32_t a[2][4], b[4][4];
      ldsm_x4(a[0], sbase + aOff[0] + ko);
      ldsm_x4(a[1], sbase + aOff[1] + ko);
#pragma unroll
      for (int q = 0; q < 4; ++q) ldsm_x4(b[q], sbase + bOff[q] + ko);
#pragma unroll
      for (int q = 0; q < 4; ++q)
#pragma unroll
        for (int mi = 0; mi < 2; ++mi) {
          mma_f16(acc[mi][2 * q],     a[mi], b[q][0], b[q][1]);
          mma_f16(acc[mi][2 * q + 1], a[mi], b[q][2], b[q][3]);
        }
    }
  }

  float* Cn = Cbase + (long long)n * 65536;
#pragma unroll
  for (int mi = 0; mi < 2; ++mi) {
    int r0 = mt * 128 + wm + mi * 16 + grp;
#pragma unroll
    for (int ni = 0; ni < 8; ++ni) {
      int col = nt * 128 + wn + ni * 8 + 2 * tg;
      float v0 = fmaxf(acc[mi][ni][0] + bias[r0 * 256 + col], 0.f);
      float v1 = fmaxf(acc[mi][ni][1] + bias[r0 * 256 + col + 1], 0.f);
      float v2 = fmaxf(acc[mi][ni][2] + bias[(r0 + 8) * 256 + col], 0.f);
      float v3 = fmaxf(acc[mi][ni][3] + bias[(r0 + 8) * 256 + col + 1], 0.f);
      *(float2*)(Cn + (long long)r0 * 256 + col) = make_float2(v0, v1);
      *(float2*)(Cn + (long long)(r0 + 8) * 256 + col) = make_float2(v2, v3);
    }
  }
}

// ---------------- launch ----------------
extern "C" void kernel_launch(void* const* d_in, const int* in_sizes, int n_in,
                              void* d_out, int out_size) {
  const float* x    = (const float*)d_in[0];
  const float* G1   = (const float*)d_in[1];
  const float* G2   = (const float*)d_in[2];
  const float* G3   = (const float*)d_in[3];
  const float* G4   = (const float*)d_in[4];
  const float* bias = (const float*)d_in[5];
  float* out = (float*)d_out;
  const int nb = in_sizes[0] / 65536;

  __half *pH34, *pH12, *pM1, *pXr;
  cudaGetSymbolAddress((void**)&pH34, g_H34);
  cudaGetSymbolAddress((void**)&pH12, g_H12);
  cudaGetSymbolAddress((void**)&pM1, g_M1);
  cudaGetSymbolAddress((void**)&pXr, g_Xr);

  const int smem1 = (A_RES_H + 4 * B_STG_H) * 2;  // 108544 B
  const int smem2 = 3 * STG64_H * 2;              // 110592 B
  cudaFuncSetAttribute(tt_gemm1, cudaFuncAttributeMaxDynamicSharedMemorySize, smem1);
  cudaFuncSetAttribute(tt_gemm2, cudaFuncAttributeMaxDynamicSharedMemorySize, smem2);

  // merged precompute: 1024 (H34) + 1024 (H12) + x/1024 (round_x) blocks
  prep_all<<<2048 + in_sizes[0] / 1024, 256>>>(G1, G2, G3, G4, x);

  // GEMM1: grid (8 mtiles x 2 ntiles, nb/NGRP sample-groups)
  tt_gemm1<<<dim3(16, nb / NGRP), 256, smem1>>>(pH34, pXr, pM1);
  // GEMM2: grid (2 mtiles x 2 ntiles, nb samples)
  tt_gemm2<<<dim3(4, nb), 256, smem2>>>(pH12, pM1, out, bias);
}